// round 1
// baseline (speedup 1.0000x reference)
#include <cuda_runtime.h>
#include <cuda_bf16.h>
#include <math.h>

// Problem constants
#define T_SEQ   2048
#define C_EMB   2048
#define N_HEADS 16
#define N_KVH   4
#define HEAD_D  128
#define KV_W    (N_KVH * HEAD_D)   // 512

// -------- scratch (device globals; no allocation allowed) --------
__device__ float g_q[T_SEQ * C_EMB];        // [T, H*D]   16 MB
__device__ float g_k[T_SEQ * KV_W];         // [T, Hkv*D]  4 MB
__device__ float g_v[T_SEQ * KV_W];         // [T, Hkv*D]  4 MB
__device__ float g_y[T_SEQ * C_EMB];        // attention out [T, H*D] 16 MB

// =====================================================================
// SGEMM: C[M,N] = A[M,K] @ B[K,N] (+ bias). 128x128 tile, BK=8,
// 256 threads, 8x8 per-thread microkernel. M,N multiples of 128, K of 8.
// =====================================================================
__global__ __launch_bounds__(256)
void sgemm128(const float* __restrict__ A, const float* __restrict__ B,
              const float* __restrict__ bias, float* __restrict__ C,
              int M, int N, int K)
{
    __shared__ float As[8][128];
    __shared__ float Bs[8][128];

    const int tid = threadIdx.x;
    const int m0 = blockIdx.y * 128;
    const int n0 = blockIdx.x * 128;
    const int tx = tid % 16;            // N direction
    const int ty = tid / 16;            // M direction

    const int a_row = tid >> 1;         // 0..127
    const int a_col = (tid & 1) * 4;    // 0 or 4
    const int b_row = tid >> 5;         // 0..7
    const int b_col = (tid & 31) * 4;   // 0..124

    const float* Aptr = A + (size_t)(m0 + a_row) * K + a_col;
    const float* Bptr = B + (size_t)b_row * N + n0 + b_col;

    float acc[8][8];
#pragma unroll
    for (int i = 0; i < 8; i++)
#pragma unroll
        for (int j = 0; j < 8; j++) acc[i][j] = 0.f;

    for (int k0 = 0; k0 < K; k0 += 8) {
        float4 av = *(const float4*)(Aptr + k0);
        As[a_col + 0][a_row] = av.x;
        As[a_col + 1][a_row] = av.y;
        As[a_col + 2][a_row] = av.z;
        As[a_col + 3][a_row] = av.w;
        float4 bv = *(const float4*)(Bptr + (size_t)k0 * N);
        *(float4*)&Bs[b_row][b_col] = bv;
        __syncthreads();

#pragma unroll
        for (int k = 0; k < 8; k++) {
            float ra[8], rb[8];
#pragma unroll
            for (int i = 0; i < 4; i++) {
                float4 v4 = *(const float4*)&As[k][ty * 8 + i * 4];
                ra[i * 4 + 0] = v4.x; ra[i * 4 + 1] = v4.y;
                ra[i * 4 + 2] = v4.z; ra[i * 4 + 3] = v4.w;
            }
#pragma unroll
            for (int j = 0; j < 4; j++) {
                float4 v4 = *(const float4*)&Bs[k][tx * 8 + j * 4];
                rb[j * 4 + 0] = v4.x; rb[j * 4 + 1] = v4.y;
                rb[j * 4 + 2] = v4.z; rb[j * 4 + 3] = v4.w;
            }
#pragma unroll
            for (int i = 0; i < 8; i++)
#pragma unroll
                for (int j = 0; j < 8; j++)
                    acc[i][j] += ra[i] * rb[j];
        }
        __syncthreads();
    }

#pragma unroll
    for (int i = 0; i < 8; i++) {
        int m = m0 + ty * 8 + i;
#pragma unroll
        for (int j = 0; j < 8; j += 4) {
            int n = n0 + tx * 8 + j;
            float4 o;
            float b0 = bias ? bias[n + 0] : 0.f;
            float b1 = bias ? bias[n + 1] : 0.f;
            float b2 = bias ? bias[n + 2] : 0.f;
            float b3 = bias ? bias[n + 3] : 0.f;
            o.x = acc[i][j + 0] + b0;
            o.y = acc[i][j + 1] + b1;
            o.z = acc[i][j + 2] + b2;
            o.w = acc[i][j + 3] + b3;
            *(float4*)&C[(size_t)m * N + n] = o;
        }
    }
}

// =====================================================================
// Multi-section RoPE. sections = [16,24,24,16,24,24], section i uses
// cos/sin channel (i % 3). cos/sin: [3, 1, T, D] contiguous.
// Applied in-place to g_q (16 heads) and g_k (4 heads); also writes
// present_k [Hkv, T, D] (post-rope).
// =====================================================================
__device__ __forceinline__ int sec3(int d) {
    // boundaries: 16,40,64,80,104,128 -> i%3 = 0,1,2,0,1,2
    if (d < 16)  return 0;
    if (d < 40)  return 1;
    if (d < 64)  return 2;
    if (d < 80)  return 0;
    if (d < 104) return 1;
    return 2;
}

__global__ __launch_bounds__(64)
void rope_kernel(const float* __restrict__ cosb, const float* __restrict__ sinb,
                 float* __restrict__ out_k)
{
    const int unit = blockIdx.x;                // T * (H + Hkv) units
    const int t = unit / (N_HEADS + N_KVH);
    const int hh = unit % (N_HEADS + N_KVH);
    const int d = threadIdx.x;                  // 0..63
    const int d2 = d + 64;

    const float c1 = cosb[(size_t)sec3(d)  * T_SEQ * HEAD_D + (size_t)t * HEAD_D + d];
    const float s1 = sinb[(size_t)sec3(d)  * T_SEQ * HEAD_D + (size_t)t * HEAD_D + d];
    const float c2 = cosb[(size_t)sec3(d2) * T_SEQ * HEAD_D + (size_t)t * HEAD_D + d2];
    const float s2 = sinb[(size_t)sec3(d2) * T_SEQ * HEAD_D + (size_t)t * HEAD_D + d2];

    float* base;
    if (hh < N_HEADS) base = g_q + (size_t)t * C_EMB + hh * HEAD_D;
    else              base = g_k + (size_t)t * KV_W + (hh - N_HEADS) * HEAD_D;

    float x1 = base[d];
    float x2 = base[d2];
    float r1 = x1 * c1 - x2 * s1;   // d < 64:  x*c + (-x[d+64])*s
    float r2 = x2 * c2 + x1 * s2;   // d >= 64: x*c + x[d-64]*s
    base[d]  = r1;
    base[d2] = r2;

    if (hh >= N_HEADS) {
        int h = hh - N_HEADS;
        out_k[(size_t)h * T_SEQ * HEAD_D + (size_t)t * HEAD_D + d]  = r1;
        out_k[(size_t)h * T_SEQ * HEAD_D + (size_t)t * HEAD_D + d2] = r2;
    }
}

// present_v copy: [T, Hkv*D] -> [Hkv, T, D]
__global__ __launch_bounds__(256)
void vcopy_kernel(float* __restrict__ out_v)
{
    int idx = blockIdx.x * 256 + threadIdx.x;   // over Hkv*T*D = 1M
    if (idx >= N_KVH * T_SEQ * HEAD_D) return;
    int d = idx & (HEAD_D - 1);
    int t = (idx / HEAD_D) & (T_SEQ - 1);
    int h = idx / (HEAD_D * T_SEQ);
    out_v[idx] = g_v[(size_t)t * KV_W + h * HEAD_D + d];
}

// =====================================================================
// Causal attention, online softmax. One warp per query row, 16 warps
// per block (16 consecutive rows, same head). 32-key K/V tiles staged
// in smem and shared by all 16 warps.
// =====================================================================
#define AT_WARPS 16

__global__ __launch_bounds__(AT_WARPS * 32)
void attn_kernel(float* __restrict__ Y)
{
    __shared__ float Ks[32][128];
    __shared__ float Vs[32][128];

    const int h = blockIdx.y;
    const int kvh = h >> 2;                    // repeat_interleave: h -> h / (H/Hkv)
    const int warp = threadIdx.x >> 5;
    const int lane = threadIdx.x & 31;
    const int t0 = blockIdx.x * AT_WARPS;
    const int t = t0 + warp;

    const float scale = 0.08838834764831845f;  // 1/sqrt(128)

    float4 q = *(const float4*)&g_q[(size_t)t * C_EMB + h * HEAD_D + lane * 4];

    float m = -1e30f, l = 0.f;
    float4 o = make_float4(0.f, 0.f, 0.f, 0.f);

    const int tmax = t0 + AT_WARPS - 1;
    for (int kk0 = 0; kk0 <= tmax; kk0 += 32) {
        // cooperative tile load: 32 keys x 128 (T multiple of 32 => in-bounds)
        for (int i = threadIdx.x; i < 32 * 32; i += AT_WARPS * 32) {
            int row = i >> 5;
            int c4 = (i & 31) * 4;
            *(float4*)&Ks[row][c4] =
                *(const float4*)&g_k[(size_t)(kk0 + row) * KV_W + kvh * HEAD_D + c4];
            *(float4*)&Vs[row][c4] =
                *(const float4*)&g_v[(size_t)(kk0 + row) * KV_W + kvh * HEAD_D + c4];
        }
        __syncthreads();

        int jend = t - kk0 + 1;
        if (jend > 32) jend = 32;
        for (int j = 0; j < jend; j++) {
            float4 kv = *(const float4*)&Ks[j][lane * 4];
            float s = q.x * kv.x + q.y * kv.y + q.z * kv.z + q.w * kv.w;
            s += __shfl_xor_sync(0xffffffffu, s, 16);
            s += __shfl_xor_sync(0xffffffffu, s, 8);
            s += __shfl_xor_sync(0xffffffffu, s, 4);
            s += __shfl_xor_sync(0xffffffffu, s, 2);
            s += __shfl_xor_sync(0xffffffffu, s, 1);
            s *= scale;

            float mn = fmaxf(m, s);
            float p = __expf(s - mn);
            float corr = __expf(m - mn);
            l = l * corr + p;
            float4 vv = *(const float4*)&Vs[j][lane * 4];
            o.x = o.x * corr + p * vv.x;
            o.y = o.y * corr + p * vv.y;
            o.z = o.z * corr + p * vv.z;
            o.w = o.w * corr + p * vv.w;
            m = mn;
        }
        __syncthreads();
    }

    float inv = 1.f / l;
    o.x *= inv; o.y *= inv; o.z *= inv; o.w *= inv;
    *(float4*)&Y[(size_t)t * C_EMB + h * HEAD_D + lane * 4] = o;
}

// =====================================================================
// launch
// =====================================================================
extern "C" void kernel_launch(void* const* d_in, const int* in_sizes, int n_in,
                              void* d_out, int out_size)
{
    (void)in_sizes; (void)n_in; (void)out_size;
    const float* x    = (const float*)d_in[0];
    const float* cosb = (const float*)d_in[1];
    const float* sinb = (const float*)d_in[2];
    const float* Wq   = (const float*)d_in[3];
    const float* bq   = (const float*)d_in[4];
    const float* Wk   = (const float*)d_in[5];
    const float* bk   = (const float*)d_in[6];
    const float* Wv   = (const float*)d_in[7];
    const float* bv   = (const float*)d_in[8];
    const float* Wo   = (const float*)d_in[9];

    float* out   = (float*)d_out;
    float* out_y = out;                                   // 2048*2048
    float* out_k = out + (size_t)T_SEQ * C_EMB;           // 4*2048*128
    float* out_v = out_k + (size_t)N_KVH * T_SEQ * HEAD_D;

    float* qb; cudaGetSymbolAddress((void**)&qb, g_q);
    float* kb; cudaGetSymbolAddress((void**)&kb, g_k);
    float* vb; cudaGetSymbolAddress((void**)&vb, g_v);
    float* yb; cudaGetSymbolAddress((void**)&yb, g_y);

    // QKV projections
    {
        dim3 gq(C_EMB / 128, T_SEQ / 128);
        sgemm128<<<gq, 256>>>(x, Wq, bq, qb, T_SEQ, C_EMB, C_EMB);
        dim3 gkv(KV_W / 128, T_SEQ / 128);
        sgemm128<<<gkv, 256>>>(x, Wk, bk, kb, T_SEQ, KV_W, C_EMB);
        sgemm128<<<gkv, 256>>>(x, Wv, bv, vb, T_SEQ, KV_W, C_EMB);
    }

    // RoPE (also writes present_k)
    rope_kernel<<<T_SEQ * (N_HEADS + N_KVH), 64>>>(cosb, sinb, out_k);

    // present_v
    vcopy_kernel<<<(N_KVH * T_SEQ * HEAD_D + 255) / 256, 256>>>(out_v);

    // causal attention
    {
        dim3 g(T_SEQ / AT_WARPS, N_HEADS);
        attn_kernel<<<g, AT_WARPS * 32>>>(yb);
    }

    // output projection -> y
    {
        dim3 go(C_EMB / 128, T_SEQ / 128);
        sgemm128<<<go, 256>>>(yb, Wo, nullptr, out_y, T_SEQ, C_EMB, C_EMB);
    }
}

// round 2
// speedup vs baseline: 1.2797x; 1.2797x over previous
#include <cuda_runtime.h>
#include <cuda_bf16.h>
#include <math.h>

// Problem constants
#define T_SEQ   2048
#define C_EMB   2048
#define N_HEADS 16
#define N_KVH   4
#define HEAD_D  128
#define KV_W    (N_KVH * HEAD_D)   // 512

// -------- scratch (device globals; no allocation allowed) --------
__device__ float g_q[T_SEQ * C_EMB];        // [T, H*D]   16 MB
__device__ float g_k[T_SEQ * KV_W];         // [T, Hkv*D]  4 MB
__device__ float g_v[T_SEQ * KV_W];         // [T, Hkv*D]  4 MB
__device__ float g_y[T_SEQ * C_EMB];        // attention out [T, H*D] 16 MB

// =====================================================================
// tf32 tensor-core GEMM: C[M,N] = A[M,K] @ B[K,N] (+bias)
// 128x128 tile, BK=32, 256 threads (8 warps, 2x4 warp grid, 64x32/warp)
// mma.sync.aligned.m16n8k8.row.col.f32.tf32.tf32.f32
// M,N multiples of 128, K multiple of 32.
// =====================================================================
#define BM 128
#define BN 128
#define BK 32
#define SPAD 136   // row stride in words: (8*tg + g) banks distinct

__device__ __forceinline__ unsigned f2tf(float x) {
    unsigned u;
    asm("cvt.rna.tf32.f32 %0, %1;" : "=r"(u) : "f"(x));
    return u;
}

__device__ __forceinline__ void mma_tf32(float* c, const unsigned* a, const unsigned* b) {
    asm volatile(
        "mma.sync.aligned.m16n8k8.row.col.f32.tf32.tf32.f32 "
        "{%0,%1,%2,%3}, {%4,%5,%6,%7}, {%8,%9}, {%0,%1,%2,%3};"
        : "+f"(c[0]), "+f"(c[1]), "+f"(c[2]), "+f"(c[3])
        : "r"(a[0]), "r"(a[1]), "r"(a[2]), "r"(a[3]), "r"(b[0]), "r"(b[1]));
}

__global__ __launch_bounds__(256)
void gemm_tf32(const float* __restrict__ A, const float* __restrict__ B,
               const float* __restrict__ bias, float* __restrict__ C,
               int M, int N, int K)
{
    __shared__ unsigned As[BK][SPAD];
    __shared__ unsigned Bs[BK][SPAD];

    const int tid  = threadIdx.x;
    const int m0   = blockIdx.y * BM;
    const int n0   = blockIdx.x * BN;
    const int warp = tid >> 5;
    const int lane = tid & 31;
    const int g    = lane >> 2;   // 0..7
    const int tg   = lane & 3;    // 0..3
    const int wm   = warp >> 2;   // 0..1
    const int wn   = warp & 3;    // 0..3

    // A loader: thread covers (m = tid&127, k-quad base = (tid>>7)*4), 4 passes step 8
    const int am  = tid & 127;
    const int akq = (tid >> 7) * 4;
    // B loader: thread covers (k = tid>>5, n4 = (tid&31)*4), 4 passes step 8
    const int bn4 = (tid & 31) * 4;
    const int bk  = tid >> 5;

    float acc[4][4][4];
#pragma unroll
    for (int mt = 0; mt < 4; mt++)
#pragma unroll
        for (int nt = 0; nt < 4; nt++)
#pragma unroll
            for (int r = 0; r < 4; r++) acc[mt][nt][r] = 0.f;

    const int KT = K / BK;
    float4 pa[4], pb[4];

    // prefetch tile kt into registers
    const float* Abase = A + (size_t)(m0 + am) * K + akq;
    const float* Bbase = B + n0 + bn4;

#pragma unroll
    for (int p = 0; p < 4; p++) pa[p] = *(const float4*)(Abase + p * 8);
#pragma unroll
    for (int p = 0; p < 4; p++) pb[p] = *(const float4*)(Bbase + (size_t)(bk + p * 8) * N);

    for (int kt = 0; kt < KT; kt++) {
        // store current prefetch to smem (with tf32 rounding)
#pragma unroll
        for (int p = 0; p < 4; p++) {
            int k = akq + p * 8;
            As[k + 0][am] = f2tf(pa[p].x);
            As[k + 1][am] = f2tf(pa[p].y);
            As[k + 2][am] = f2tf(pa[p].z);
            As[k + 3][am] = f2tf(pa[p].w);
        }
#pragma unroll
        for (int p = 0; p < 4; p++) {
            int k = bk + p * 8;
            uint4 u;
            u.x = f2tf(pb[p].x); u.y = f2tf(pb[p].y);
            u.z = f2tf(pb[p].z); u.w = f2tf(pb[p].w);
            *(uint4*)&Bs[k][bn4] = u;
        }
        __syncthreads();

        // prefetch next tile
        if (kt + 1 < KT) {
            const float* An = Abase + (size_t)(kt + 1) * BK;
#pragma unroll
            for (int p = 0; p < 4; p++) pa[p] = *(const float4*)(An + p * 8);
#pragma unroll
            for (int p = 0; p < 4; p++)
                pb[p] = *(const float4*)(Bbase + (size_t)((kt + 1) * BK + bk + p * 8) * N);
        }

        // compute: 4 k-chunks of 8
#pragma unroll
        for (int kc = 0; kc < 4; kc++) {
            const int k = kc * 8;
            unsigned af[4][4], bf[4][2];
#pragma unroll
            for (int mt = 0; mt < 4; mt++) {
                int r = wm * 64 + mt * 16;
                af[mt][0] = As[k + tg][r + g];
                af[mt][1] = As[k + tg][r + g + 8];
                af[mt][2] = As[k + tg + 4][r + g];
                af[mt][3] = As[k + tg + 4][r + g + 8];
            }
#pragma unroll
            for (int nt = 0; nt < 4; nt++) {
                int c = wn * 32 + nt * 8 + g;
                bf[nt][0] = Bs[k + tg][c];
                bf[nt][1] = Bs[k + tg + 4][c];
            }
#pragma unroll
            for (int mt = 0; mt < 4; mt++)
#pragma unroll
                for (int nt = 0; nt < 4; nt++)
                    mma_tf32(acc[mt][nt], af[mt], bf[nt]);
        }
        __syncthreads();
    }

    // epilogue
#pragma unroll
    for (int mt = 0; mt < 4; mt++) {
        int r0 = m0 + wm * 64 + mt * 16 + g;
#pragma unroll
        for (int nt = 0; nt < 4; nt++) {
            int c = n0 + wn * 32 + nt * 8 + 2 * tg;
            float bx = 0.f, by = 0.f;
            if (bias) { bx = bias[c]; by = bias[c + 1]; }
            float2 v0 = make_float2(acc[mt][nt][0] + bx, acc[mt][nt][1] + by);
            float2 v1 = make_float2(acc[mt][nt][2] + bx, acc[mt][nt][3] + by);
            *(float2*)&C[(size_t)r0 * N + c]       = v0;
            *(float2*)&C[(size_t)(r0 + 8) * N + c] = v1;
        }
    }
}

// =====================================================================
// Multi-section RoPE. sections = [16,24,24,16,24,24], section i uses
// cos/sin channel (i % 3). cos/sin: [3, 1, T, D] contiguous.
// =====================================================================
__device__ __forceinline__ int sec3(int d) {
    if (d < 16)  return 0;
    if (d < 40)  return 1;
    if (d < 64)  return 2;
    if (d < 80)  return 0;
    if (d < 104) return 1;
    return 2;
}

__global__ __launch_bounds__(64)
void rope_kernel(const float* __restrict__ cosb, const float* __restrict__ sinb,
                 float* __restrict__ out_k)
{
    const int unit = blockIdx.x;
    const int t  = unit / (N_HEADS + N_KVH);
    const int hh = unit % (N_HEADS + N_KVH);
    const int d  = threadIdx.x;
    const int d2 = d + 64;

    const float c1 = cosb[(size_t)sec3(d)  * T_SEQ * HEAD_D + (size_t)t * HEAD_D + d];
    const float s1 = sinb[(size_t)sec3(d)  * T_SEQ * HEAD_D + (size_t)t * HEAD_D + d];
    const float c2 = cosb[(size_t)sec3(d2) * T_SEQ * HEAD_D + (size_t)t * HEAD_D + d2];
    const float s2 = sinb[(size_t)sec3(d2) * T_SEQ * HEAD_D + (size_t)t * HEAD_D + d2];

    float* base;
    if (hh < N_HEADS) base = g_q + (size_t)t * C_EMB + hh * HEAD_D;
    else              base = g_k + (size_t)t * KV_W + (hh - N_HEADS) * HEAD_D;

    float x1 = base[d];
    float x2 = base[d2];
    float r1 = x1 * c1 - x2 * s1;
    float r2 = x2 * c2 + x1 * s2;
    base[d]  = r1;
    base[d2] = r2;

    if (hh >= N_HEADS) {
        int h = hh - N_HEADS;
        out_k[(size_t)h * T_SEQ * HEAD_D + (size_t)t * HEAD_D + d]  = r1;
        out_k[(size_t)h * T_SEQ * HEAD_D + (size_t)t * HEAD_D + d2] = r2;
    }
}

// present_v copy: [T, Hkv*D] -> [Hkv, T, D]
__global__ __launch_bounds__(256)
void vcopy_kernel(float* __restrict__ out_v)
{
    int idx = blockIdx.x * 256 + threadIdx.x;
    if (idx >= N_KVH * T_SEQ * HEAD_D) return;
    int d = idx & (HEAD_D - 1);
    int t = (idx / HEAD_D) & (T_SEQ - 1);
    int h = idx / (HEAD_D * T_SEQ);
    out_v[idx] = g_v[(size_t)t * KV_W + h * HEAD_D + d];
}

// =====================================================================
// Causal attention, two-pass tile softmax. One warp per query row,
// 16 warps/block, 32-key K/V smem tiles shared by all warps.
// Pass 1: scores (lane j keeps s_j); one tile-max reduce; ONE exp/lane.
// Pass 2: broadcast p_j via shfl, accumulate V.
// =====================================================================
#define AT_WARPS 16

__global__ __launch_bounds__(AT_WARPS * 32)
void attn_kernel(float* __restrict__ Y)
{
    __shared__ float Ks[32][128];
    __shared__ float Vs[32][128];

    const int h    = blockIdx.y;
    const int kvh  = h >> 2;
    const int warp = threadIdx.x >> 5;
    const int lane = threadIdx.x & 31;
    const int t0   = blockIdx.x * AT_WARPS;
    const int t    = t0 + warp;

    const float scale = 0.08838834764831845f;

    float4 q = *(const float4*)&g_q[(size_t)t * C_EMB + h * HEAD_D + lane * 4];

    float m = -1e30f, l = 0.f;
    float4 o = make_float4(0.f, 0.f, 0.f, 0.f);

    const int tmax = t0 + AT_WARPS - 1;
    for (int kk0 = 0; kk0 <= tmax; kk0 += 32) {
        for (int i = threadIdx.x; i < 32 * 32; i += AT_WARPS * 32) {
            int row = i >> 5;
            int c4  = (i & 31) * 4;
            *(float4*)&Ks[row][c4] =
                *(const float4*)&g_k[(size_t)(kk0 + row) * KV_W + kvh * HEAD_D + c4];
            *(float4*)&Vs[row][c4] =
                *(const float4*)&g_v[(size_t)(kk0 + row) * KV_W + kvh * HEAD_D + c4];
        }
        __syncthreads();

        int jend = t - kk0 + 1;
        if (jend > 32) jend = 32;

        if (jend > 0) {
            // ---- pass 1: scores, lane j keeps s_j ----
            float skeep = -1e30f;
            if (jend == 32) {
#pragma unroll
                for (int j = 0; j < 32; j++) {
                    float4 kv = *(const float4*)&Ks[j][lane * 4];
                    float s = q.x * kv.x + q.y * kv.y + q.z * kv.z + q.w * kv.w;
                    s += __shfl_xor_sync(0xffffffffu, s, 16);
                    s += __shfl_xor_sync(0xffffffffu, s, 8);
                    s += __shfl_xor_sync(0xffffffffu, s, 4);
                    s += __shfl_xor_sync(0xffffffffu, s, 2);
                    s += __shfl_xor_sync(0xffffffffu, s, 1);
                    skeep = (lane == j) ? s * scale : skeep;
                }
            } else {
                for (int j = 0; j < jend; j++) {
                    float4 kv = *(const float4*)&Ks[j][lane * 4];
                    float s = q.x * kv.x + q.y * kv.y + q.z * kv.z + q.w * kv.w;
                    s += __shfl_xor_sync(0xffffffffu, s, 16);
                    s += __shfl_xor_sync(0xffffffffu, s, 8);
                    s += __shfl_xor_sync(0xffffffffu, s, 4);
                    s += __shfl_xor_sync(0xffffffffu, s, 2);
                    s += __shfl_xor_sync(0xffffffffu, s, 1);
                    skeep = (lane == j) ? s * scale : skeep;
                }
            }

            // ---- tile max, single exp per lane ----
            float tm = skeep;
            tm = fmaxf(tm, __shfl_xor_sync(0xffffffffu, tm, 16));
            tm = fmaxf(tm, __shfl_xor_sync(0xffffffffu, tm, 8));
            tm = fmaxf(tm, __shfl_xor_sync(0xffffffffu, tm, 4));
            tm = fmaxf(tm, __shfl_xor_sync(0xffffffffu, tm, 2));
            tm = fmaxf(tm, __shfl_xor_sync(0xffffffffu, tm, 1));

            float mn   = fmaxf(m, tm);
            float corr = __expf(m - mn);
            float p    = __expf(skeep - mn);   // masked lanes: exp(very negative)=0

            float ps = p;
            ps += __shfl_xor_sync(0xffffffffu, ps, 16);
            ps += __shfl_xor_sync(0xffffffffu, ps, 8);
            ps += __shfl_xor_sync(0xffffffffu, ps, 4);
            ps += __shfl_xor_sync(0xffffffffu, ps, 2);
            ps += __shfl_xor_sync(0xffffffffu, ps, 1);

            l = l * corr + ps;
            o.x *= corr; o.y *= corr; o.z *= corr; o.w *= corr;
            m = mn;

            // ---- pass 2: accumulate V ----
            if (jend == 32) {
#pragma unroll
                for (int j = 0; j < 32; j++) {
                    float pj = __shfl_sync(0xffffffffu, p, j);
                    float4 vv = *(const float4*)&Vs[j][lane * 4];
                    o.x += pj * vv.x; o.y += pj * vv.y;
                    o.z += pj * vv.z; o.w += pj * vv.w;
                }
            } else {
                for (int j = 0; j < jend; j++) {
                    float pj = __shfl_sync(0xffffffffu, p, j);
                    float4 vv = *(const float4*)&Vs[j][lane * 4];
                    o.x += pj * vv.x; o.y += pj * vv.y;
                    o.z += pj * vv.z; o.w += pj * vv.w;
                }
            }
        }
        __syncthreads();
    }

    float inv = 1.f / l;
    o.x *= inv; o.y *= inv; o.z *= inv; o.w *= inv;
    *(float4*)&Y[(size_t)t * C_EMB + h * HEAD_D + lane * 4] = o;
}

// =====================================================================
// launch
// =====================================================================
extern "C" void kernel_launch(void* const* d_in, const int* in_sizes, int n_in,
                              void* d_out, int out_size)
{
    (void)in_sizes; (void)n_in; (void)out_size;
    const float* x    = (const float*)d_in[0];
    const float* cosb = (const float*)d_in[1];
    const float* sinb = (const float*)d_in[2];
    const float* Wq   = (const float*)d_in[3];
    const float* bq   = (const float*)d_in[4];
    const float* Wk   = (const float*)d_in[5];
    const float* bk   = (const float*)d_in[6];
    const float* Wv   = (const float*)d_in[7];
    const float* bv   = (const float*)d_in[8];
    const float* Wo   = (const float*)d_in[9];

    float* out   = (float*)d_out;
    float* out_y = out;
    float* out_k = out + (size_t)T_SEQ * C_EMB;
    float* out_v = out_k + (size_t)N_KVH * T_SEQ * HEAD_D;

    float* qb; cudaGetSymbolAddress((void**)&qb, g_q);
    float* kb; cudaGetSymbolAddress((void**)&kb, g_k);
    float* vb; cudaGetSymbolAddress((void**)&vb, g_v);
    float* yb; cudaGetSymbolAddress((void**)&yb, g_y);

    // QKV projections (tf32 tensor cores)
    {
        dim3 gq(C_EMB / BN, T_SEQ / BM);
        gemm_tf32<<<gq, 256>>>(x, Wq, bq, qb, T_SEQ, C_EMB, C_EMB);
        dim3 gkv(KV_W / BN, T_SEQ / BM);
        gemm_tf32<<<gkv, 256>>>(x, Wk, bk, kb, T_SEQ, KV_W, C_EMB);
        gemm_tf32<<<gkv, 256>>>(x, Wv, bv, vb, T_SEQ, KV_W, C_EMB);
    }

    // RoPE (also writes present_k)
    rope_kernel<<<T_SEQ * (N_HEADS + N_KVH), 64>>>(cosb, sinb, out_k);

    // present_v
    vcopy_kernel<<<(N_KVH * T_SEQ * HEAD_D + 255) / 256, 256>>>(out_v);

    // causal attention
    {
        dim3 g(T_SEQ / AT_WARPS, N_HEADS);
        attn_kernel<<<g, AT_WARPS * 32>>>(yb);
    }

    // output projection -> y
    {
        dim3 go(C_EMB / BN, T_SEQ / BM);
        gemm_tf32<<<go, 256>>>(yb, Wo, nullptr, out_y, T_SEQ, C_EMB, C_EMB);
    }
}

// round 4
// speedup vs baseline: 1.2836x; 1.0030x over previous
#include <cuda_runtime.h>
#include <cuda_bf16.h>
#include <math.h>
#include <cstdint>

// Problem constants
#define T_SEQ   2048
#define C_EMB   2048
#define N_HEADS 16
#define N_KVH   4
#define HEAD_D  128
#define KV_W    (N_KVH * HEAD_D)   // 512

// -------- scratch (device globals; no allocation allowed) --------
__device__ float g_q[T_SEQ * C_EMB];
__device__ float g_k[T_SEQ * KV_W];
__device__ float g_v[T_SEQ * KV_W];
__device__ float g_y[T_SEQ * C_EMB];        // attention out, tf32-rounded values
__device__ float g_xr[T_SEQ * C_EMB];       // x, tf32-rounded
// transposed weights [N, K] row-major (K contiguous), tf32-rounded values
__device__ float g_wqt[C_EMB * C_EMB];
__device__ float g_wkt[KV_W * C_EMB];
__device__ float g_wvt[KV_W * C_EMB];
__device__ float g_wot[C_EMB * C_EMB];

// =====================================================================
// helpers
// =====================================================================
__device__ __forceinline__ unsigned f2tf(float x) {
    unsigned u;
    asm("cvt.rna.tf32.f32 %0, %1;" : "=r"(u) : "f"(x));
    return u;
}
__device__ __forceinline__ uint32_t smem_u32(const void* p) {
    uint32_t a;
    asm("{ .reg .u64 t; cvta.to.shared.u64 t, %1; cvt.u32.u64 %0, t; }" : "=r"(a) : "l"(p));
    return a;
}
__device__ __forceinline__ void cp_async16(uint32_t dst, const void* src) {
    asm volatile("cp.async.ca.shared.global [%0], [%1], 16;" :: "r"(dst), "l"(src) : "memory");
}
__device__ __forceinline__ void cp_commit() {
    asm volatile("cp.async.commit_group;" ::: "memory");
}
template <int N>
__device__ __forceinline__ void cp_wait() {
    asm volatile("cp.async.wait_group %0;" :: "n"(N) : "memory");
}
__device__ __forceinline__ void mma_tf32(float* c, const unsigned* a, const unsigned* b) {
    asm volatile(
        "mma.sync.aligned.m16n8k8.row.col.f32.tf32.tf32.f32 "
        "{%0,%1,%2,%3}, {%4,%5,%6,%7}, {%8,%9}, {%0,%1,%2,%3};"
        : "+f"(c[0]), "+f"(c[1]), "+f"(c[2]), "+f"(c[3])
        : "r"(a[0]), "r"(a[1]), "r"(a[2]), "r"(a[3]), "r"(b[0]), "r"(b[1]));
}

// =====================================================================
// tf32 mma GEMM, cp.async 4-stage pipeline.
// C[M,N] = A[M,K] @ Bt[N,K]^T (+bias)
// A, Bt values must already be tf32-rounded (bits exact under truncation).
// CTA 128x128, BK=16, 256 threads (8 warps 2x4, warp tile 64x32).
// Smem stage: A 128 rows x 64B data padded to 80B; B same. 20KB/stage.
// =====================================================================
#define GSTAGES   4
#define GROWB     80                       // bytes per padded row
#define GROWW     20                       // words per padded row
#define STAGE_A   (128 * GROWB)            // 10240
#define STAGE_SZ  (2 * STAGE_A)            // 20480 (A then B)
#define GSMEM     (GSTAGES * STAGE_SZ)     // 81920

__global__ __launch_bounds__(256, 2)
void gemm_mma(const float* __restrict__ A, const float* __restrict__ Bt,
              const float* __restrict__ bias, float* __restrict__ C,
              int M, int N, int K)
{
    extern __shared__ char smem[];
    const uint32_t sbase = smem_u32(smem);

    const int tid  = threadIdx.x;
    const int warp = tid >> 5;
    const int lane = tid & 31;
    const int g    = lane >> 2;     // 0..7
    const int tg   = lane & 3;      // 0..3
    const int wm   = warp >> 2;     // 0..1
    const int wn   = warp & 3;      // 0..3
    const int m0   = blockIdx.y * 128;
    const int n0   = blockIdx.x * 128;

    // loader mapping: row = tid>>1, 32 bytes per thread (two 16B chunks)
    const int lrow = tid >> 1;
    const int lk   = (tid & 1) * 8;   // element offset within 16-k tile
    const float* Asrc = A  + (size_t)(m0 + lrow) * K + lk;
    const float* Bsrc = Bt + (size_t)(n0 + lrow) * K + lk;
    const uint32_t a_dst0 = (uint32_t)(lrow * GROWB + (tid & 1) * 32);
    const int KT = K / 16;

    float acc[4][4][4];
#pragma unroll
    for (int mt = 0; mt < 4; mt++)
#pragma unroll
        for (int nt = 0; nt < 4; nt++)
#pragma unroll
            for (int r = 0; r < 4; r++) acc[mt][nt][r] = 0.f;

    // ---- prologue: issue stages 0..2 ----
#pragma unroll
    for (int s = 0; s < GSTAGES - 1; s++) {
        uint32_t sa = sbase + s * STAGE_SZ + a_dst0;
        uint32_t sb = sa + STAGE_A;
        cp_async16(sa,      Asrc + (size_t)s * 16);
        cp_async16(sa + 16, Asrc + (size_t)s * 16 + 4);
        cp_async16(sb,      Bsrc + (size_t)s * 16);
        cp_async16(sb + 16, Bsrc + (size_t)s * 16 + 4);
        cp_commit();
    }

    for (int kt = 0; kt < KT; kt++) {
        cp_wait<GSTAGES - 2>();
        __syncthreads();

        // issue stage kt+3 (slot consumed at iter kt-1; safe after the sync)
        if (kt + GSTAGES - 1 < KT) {
            int s = (kt + GSTAGES - 1) & (GSTAGES - 1);
            uint32_t sa = sbase + s * STAGE_SZ + a_dst0;
            uint32_t sb = sa + STAGE_A;
            const float* Ai = Asrc + (size_t)(kt + GSTAGES - 1) * 16;
            const float* Bi = Bsrc + (size_t)(kt + GSTAGES - 1) * 16;
            cp_async16(sa,      Ai);
            cp_async16(sa + 16, Ai + 4);
            cp_async16(sb,      Bi);
            cp_async16(sb + 16, Bi + 4);
        }
        cp_commit();

        // compute on slot kt%4
        const int slot = kt & (GSTAGES - 1);
        const uint32_t* As32 = (const uint32_t*)(smem + slot * STAGE_SZ);
        const uint32_t* Bs32 = (const uint32_t*)(smem + slot * STAGE_SZ + STAGE_A);

#pragma unroll
        for (int kc = 0; kc < 2; kc++) {
            const int kb = kc * 8;
            unsigned af[4][4], bf[4][2];
#pragma unroll
            for (int mt = 0; mt < 4; mt++) {
                int r = wm * 64 + mt * 16 + g;
                af[mt][0] = As32[r * GROWW + kb + tg];
                af[mt][1] = As32[(r + 8) * GROWW + kb + tg];
                af[mt][2] = As32[r * GROWW + kb + tg + 4];
                af[mt][3] = As32[(r + 8) * GROWW + kb + tg + 4];
            }
#pragma unroll
            for (int nt = 0; nt < 4; nt++) {
                int c = wn * 32 + nt * 8 + g;
                bf[nt][0] = Bs32[c * GROWW + kb + tg];
                bf[nt][1] = Bs32[c * GROWW + kb + tg + 4];
            }
#pragma unroll
            for (int mt = 0; mt < 4; mt++)
#pragma unroll
                for (int nt = 0; nt < 4; nt++)
                    mma_tf32(acc[mt][nt], af[mt], bf[nt]);
        }
    }

    // epilogue
#pragma unroll
    for (int mt = 0; mt < 4; mt++) {
        int r0 = m0 + wm * 64 + mt * 16 + g;
#pragma unroll
        for (int nt = 0; nt < 4; nt++) {
            int c = n0 + wn * 32 + nt * 8 + 2 * tg;
            float bx = 0.f, by = 0.f;
            if (bias) { bx = bias[c]; by = bias[c + 1]; }
            float2 v0 = make_float2(acc[mt][nt][0] + bx, acc[mt][nt][1] + by);
            float2 v1 = make_float2(acc[mt][nt][2] + bx, acc[mt][nt][3] + by);
            *(float2*)&C[(size_t)r0 * N + c]       = v0;
            *(float2*)&C[(size_t)(r0 + 8) * N + c] = v1;
        }
    }
}

// =====================================================================
// x pre-round: g_xr = tf32(x)
// =====================================================================
__global__ __launch_bounds__(256)
void roundx_kernel(const float* __restrict__ x)
{
    int i = (blockIdx.x * 256 + threadIdx.x) * 4;
    float4 v = *(const float4*)&x[i];
    uint4 u;
    u.x = f2tf(v.x); u.y = f2tf(v.y); u.z = f2tf(v.z); u.w = f2tf(v.w);
    *(uint4*)&g_xr[i] = u;
}

// =====================================================================
// transpose + tf32 round: out[C,R] = tf32(in[R,C]^T)
// =====================================================================
__global__ __launch_bounds__(256)
void transpose_k(const float* __restrict__ in, float* __restrict__ out, int R, int C)
{
    __shared__ float tile[32][33];
    const int bx = blockIdx.x * 32;
    const int by = blockIdx.y * 32;
    const int x = bx + threadIdx.x;
#pragma unroll
    for (int i = threadIdx.y; i < 32; i += 8)
        tile[i][threadIdx.x] = in[(size_t)(by + i) * C + x];
    __syncthreads();
    const int ox = by + threadIdx.x;
#pragma unroll
    for (int i = threadIdx.y; i < 32; i += 8)
        ((uint32_t*)out)[(size_t)(bx + i) * R + ox] = f2tf(tile[threadIdx.x][i]);
}

// =====================================================================
// Multi-section RoPE
// =====================================================================
__device__ __forceinline__ int sec3(int d) {
    if (d < 16)  return 0;
    if (d < 40)  return 1;
    if (d < 64)  return 2;
    if (d < 80)  return 0;
    if (d < 104) return 1;
    return 2;
}

__global__ __launch_bounds__(64)
void rope_kernel(const float* __restrict__ cosb, const float* __restrict__ sinb,
                 float* __restrict__ out_k)
{
    const int unit = blockIdx.x;
    const int t  = unit / (N_HEADS + N_KVH);
    const int hh = unit % (N_HEADS + N_KVH);
    const int d  = threadIdx.x;
    const int d2 = d + 64;

    const float c1 = cosb[(size_t)sec3(d)  * T_SEQ * HEAD_D + (size_t)t * HEAD_D + d];
    const float s1 = sinb[(size_t)sec3(d)  * T_SEQ * HEAD_D + (size_t)t * HEAD_D + d];
    const float c2 = cosb[(size_t)sec3(d2) * T_SEQ * HEAD_D + (size_t)t * HEAD_D + d2];
    const float s2 = sinb[(size_t)sec3(d2) * T_SEQ * HEAD_D + (size_t)t * HEAD_D + d2];

    float* base;
    if (hh < N_HEADS) base = g_q + (size_t)t * C_EMB + hh * HEAD_D;
    else              base = g_k + (size_t)t * KV_W + (hh - N_HEADS) * HEAD_D;

    float x1 = base[d];
    float x2 = base[d2];
    float r1 = x1 * c1 - x2 * s1;
    float r2 = x2 * c2 + x1 * s2;
    base[d]  = r1;
    base[d2] = r2;

    if (hh >= N_HEADS) {
        int h = hh - N_HEADS;
        out_k[(size_t)h * T_SEQ * HEAD_D + (size_t)t * HEAD_D + d]  = r1;
        out_k[(size_t)h * T_SEQ * HEAD_D + (size_t)t * HEAD_D + d2] = r2;
    }
}

__global__ __launch_bounds__(256)
void vcopy_kernel(float* __restrict__ out_v)
{
    int idx = blockIdx.x * 256 + threadIdx.x;
    if (idx >= N_KVH * T_SEQ * HEAD_D) return;
    int d = idx & (HEAD_D - 1);
    int t = (idx / HEAD_D) & (T_SEQ - 1);
    int h = idx / (HEAD_D * T_SEQ);
    out_v[idx] = g_v[(size_t)t * KV_W + h * HEAD_D + d];
}

// =====================================================================
// Causal attention (two-pass tile softmax). Output stored tf32-rounded
// so the final GEMM can consume it without conversion.
// =====================================================================
#define AT_WARPS 16

__global__ __launch_bounds__(AT_WARPS * 32)
void attn_kernel(float* __restrict__ Y)
{
    __shared__ float Ks[32][128];
    __shared__ float Vs[32][128];

    const int h    = blockIdx.y;
    const int kvh  = h >> 2;
    const int warp = threadIdx.x >> 5;
    const int lane = threadIdx.x & 31;
    const int t0   = blockIdx.x * AT_WARPS;
    const int t    = t0 + warp;

    const float scale = 0.08838834764831845f;

    float4 q = *(const float4*)&g_q[(size_t)t * C_EMB + h * HEAD_D + lane * 4];

    float m = -1e30f, l = 0.f;
    float4 o = make_float4(0.f, 0.f, 0.f, 0.f);

    const int tmax = t0 + AT_WARPS - 1;
    for (int kk0 = 0; kk0 <= tmax; kk0 += 32) {
        for (int i = threadIdx.x; i < 32 * 32; i += AT_WARPS * 32) {
            int row = i >> 5;
            int c4  = (i & 31) * 4;
            *(float4*)&Ks[row][c4] =
                *(const float4*)&g_k[(size_t)(kk0 + row) * KV_W + kvh * HEAD_D + c4];
            *(float4*)&Vs[row][c4] =
                *(const float4*)&g_v[(size_t)(kk0 + row) * KV_W + kvh * HEAD_D + c4];
        }
        __syncthreads();

        int jend = t - kk0 + 1;
        if (jend > 32) jend = 32;

        if (jend > 0) {
            float skeep = -1e30f;
            if (jend == 32) {
#pragma unroll
                for (int j = 0; j < 32; j++) {
                    float4 kv = *(const float4*)&Ks[j][lane * 4];
                    float s = q.x * kv.x + q.y * kv.y + q.z * kv.z + q.w * kv.w;
                    s += __shfl_xor_sync(0xffffffffu, s, 16);
                    s += __shfl_xor_sync(0xffffffffu, s, 8);
                    s += __shfl_xor_sync(0xffffffffu, s, 4);
                    s += __shfl_xor_sync(0xffffffffu, s, 2);
                    s += __shfl_xor_sync(0xffffffffu, s, 1);
                    skeep = (lane == j) ? s * scale : skeep;
                }
            } else {
                for (int j = 0; j < jend; j++) {
                    float4 kv = *(const float4*)&Ks[j][lane * 4];
                    float s = q.x * kv.x + q.y * kv.y + q.z * kv.z + q.w * kv.w;
                    s += __shfl_xor_sync(0xffffffffu, s, 16);
                    s += __shfl_xor_sync(0xffffffffu, s, 8);
                    s += __shfl_xor_sync(0xffffffffu, s, 4);
                    s += __shfl_xor_sync(0xffffffffu, s, 2);
                    s += __shfl_xor_sync(0xffffffffu, s, 1);
                    skeep = (lane == j) ? s * scale : skeep;
                }
            }

            float tm = skeep;
            tm = fmaxf(tm, __shfl_xor_sync(0xffffffffu, tm, 16));
            tm = fmaxf(tm, __shfl_xor_sync(0xffffffffu, tm, 8));
            tm = fmaxf(tm, __shfl_xor_sync(0xffffffffu, tm, 4));
            tm = fmaxf(tm, __shfl_xor_sync(0xffffffffu, tm, 2));
            tm = fmaxf(tm, __shfl_xor_sync(0xffffffffu, tm, 1));

            float mn   = fmaxf(m, tm);
            float corr = __expf(m - mn);
            float p    = __expf(skeep - mn);

            float ps = p;
            ps += __shfl_xor_sync(0xffffffffu, ps, 16);
            ps += __shfl_xor_sync(0xffffffffu, ps, 8);
            ps += __shfl_xor_sync(0xffffffffu, ps, 4);
            ps += __shfl_xor_sync(0xffffffffu, ps, 2);
            ps += __shfl_xor_sync(0xffffffffu, ps, 1);

            l = l * corr + ps;
            o.x *= corr; o.y *= corr; o.z *= corr; o.w *= corr;
            m = mn;

            if (jend == 32) {
#pragma unroll
                for (int j = 0; j < 32; j++) {
                    float pj = __shfl_sync(0xffffffffu, p, j);
                    float4 vv = *(const float4*)&Vs[j][lane * 4];
                    o.x += pj * vv.x; o.y += pj * vv.y;
                    o.z += pj * vv.z; o.w += pj * vv.w;
                }
            } else {
                for (int j = 0; j < jend; j++) {
                    float pj = __shfl_sync(0xffffffffu, p, j);
                    float4 vv = *(const float4*)&Vs[j][lane * 4];
                    o.x += pj * vv.x; o.y += pj * vv.y;
                    o.z += pj * vv.z; o.w += pj * vv.w;
                }
            }
        }
        __syncthreads();
    }

    float inv = 1.f / l;
    uint4 u;
    u.x = f2tf(o.x * inv); u.y = f2tf(o.y * inv);
    u.z = f2tf(o.z * inv); u.w = f2tf(o.w * inv);
    *(uint4*)&Y[(size_t)t * C_EMB + h * HEAD_D + lane * 4] = u;
}

// =====================================================================
// launch
// =====================================================================
extern "C" void kernel_launch(void* const* d_in, const int* in_sizes, int n_in,
                              void* d_out, int out_size)
{
    (void)in_sizes; (void)n_in; (void)out_size;
    const float* x    = (const float*)d_in[0];
    const float* cosb = (const float*)d_in[1];
    const float* sinb = (const float*)d_in[2];
    const float* Wq   = (const float*)d_in[3];
    const float* bq   = (const float*)d_in[4];
    const float* Wk   = (const float*)d_in[5];
    const float* bk   = (const float*)d_in[6];
    const float* Wv   = (const float*)d_in[7];
    const float* bv   = (const float*)d_in[8];
    const float* Wo   = (const float*)d_in[9];

    float* out   = (float*)d_out;
    float* out_y = out;
    float* out_k = out + (size_t)T_SEQ * C_EMB;
    float* out_v = out_k + (size_t)N_KVH * T_SEQ * HEAD_D;

    float* qb;  cudaGetSymbolAddress((void**)&qb,  g_q);
    float* kb;  cudaGetSymbolAddress((void**)&kb,  g_k);
    float* vb;  cudaGetSymbolAddress((void**)&vb,  g_v);
    float* yb;  cudaGetSymbolAddress((void**)&yb,  g_y);
    float* xrb; cudaGetSymbolAddress((void**)&xrb, g_xr);
    float* wqt; cudaGetSymbolAddress((void**)&wqt, g_wqt);
    float* wkt; cudaGetSymbolAddress((void**)&wkt, g_wkt);
    float* wvt; cudaGetSymbolAddress((void**)&wvt, g_wvt);
    float* wot; cudaGetSymbolAddress((void**)&wot, g_wot);

    cudaFuncSetAttribute(gemm_mma, cudaFuncAttributeMaxDynamicSharedMemorySize, GSMEM);

    // 1: x -> tf32
    roundx_kernel<<<(T_SEQ * C_EMB / 4) / 256, 256>>>(x);

    // 2-5: weight transposes (+tf32 round)
    {
        dim3 blk(32, 8);
        transpose_k<<<dim3(C_EMB / 32, C_EMB / 32), blk>>>(Wq, wqt, C_EMB, C_EMB);
        transpose_k<<<dim3(KV_W / 32, C_EMB / 32), blk>>>(Wk, wkt, C_EMB, KV_W);
        transpose_k<<<dim3(KV_W / 32, C_EMB / 32), blk>>>(Wv, wvt, C_EMB, KV_W);
        transpose_k<<<dim3(C_EMB / 32, C_EMB / 32), blk>>>(Wo, wot, C_EMB, C_EMB);
    }

    // 6: gemmQ  (this is the launch ncu captures: -s 5 -c 1)
    gemm_mma<<<dim3(C_EMB / 128, T_SEQ / 128), 256, GSMEM>>>(xrb, wqt, bq, qb, T_SEQ, C_EMB, C_EMB);
    // 7-8: gemmK, gemmV
    gemm_mma<<<dim3(KV_W / 128, T_SEQ / 128), 256, GSMEM>>>(xrb, wkt, bk, kb, T_SEQ, KV_W, C_EMB);
    gemm_mma<<<dim3(KV_W / 128, T_SEQ / 128), 256, GSMEM>>>(xrb, wvt, bv, vb, T_SEQ, KV_W, C_EMB);

    // 9: RoPE (also writes present_k)
    rope_kernel<<<T_SEQ * (N_HEADS + N_KVH), 64>>>(cosb, sinb, out_k);

    // 10: present_v
    vcopy_kernel<<<(N_KVH * T_SEQ * HEAD_D + 255) / 256, 256>>>(out_v);

    // 11: causal attention (writes tf32-rounded y)
    attn_kernel<<<dim3(T_SEQ / AT_WARPS, N_HEADS), AT_WARPS * 32>>>(yb);

    // 12: output projection
    gemm_mma<<<dim3(C_EMB / 128, T_SEQ / 128), 256, GSMEM>>>(yb, wot, nullptr, out_y, T_SEQ, C_EMB, C_EMB);
}

// round 6
// speedup vs baseline: 1.4302x; 1.1142x over previous
#include <cuda_runtime.h>
#include <cuda_fp16.h>
#include <math.h>
#include <cstdint>

// Problem constants
#define T_SEQ   2048
#define C_EMB   2048
#define N_HEADS 16
#define N_KVH   4
#define HEAD_D  128
#define KV_W    (N_KVH * HEAD_D)   // 512

// -------- scratch (device globals; no allocation allowed) --------
__device__ float  g_q[T_SEQ * C_EMB];
__device__ float  g_k[T_SEQ * KV_W];
__device__ float  g_v[T_SEQ * KV_W];
__device__ __half g_yh[T_SEQ * C_EMB];      // attention out (half, for final gemm)
__device__ __half g_xh[T_SEQ * C_EMB];      // x in half
// transposed weights [N, K] row-major (K contiguous), half
__device__ __half g_wqt[C_EMB * C_EMB];
__device__ __half g_wkt[KV_W * C_EMB];
__device__ __half g_wvt[KV_W * C_EMB];
__device__ __half g_wot[C_EMB * C_EMB];

// =====================================================================
// helpers
// =====================================================================
__device__ __forceinline__ uint32_t smem_u32(const void* p) {
    uint32_t a;
    asm("{ .reg .u64 t; cvta.to.shared.u64 t, %1; cvt.u32.u64 %0, t; }" : "=r"(a) : "l"(p));
    return a;
}
__device__ __forceinline__ void cp_async16(uint32_t dst, const void* src) {
    asm volatile("cp.async.ca.shared.global [%0], [%1], 16;" :: "r"(dst), "l"(src) : "memory");
}
__device__ __forceinline__ void cp_commit() {
    asm volatile("cp.async.commit_group;" ::: "memory");
}
template <int N>
__device__ __forceinline__ void cp_wait() {
    asm volatile("cp.async.wait_group %0;" :: "n"(N) : "memory");
}
__device__ __forceinline__ void ldm_x4(unsigned* r, uint32_t addr) {
    asm volatile("ldmatrix.sync.aligned.m8n8.x4.shared.b16 {%0,%1,%2,%3}, [%4];"
        : "=r"(r[0]), "=r"(r[1]), "=r"(r[2]), "=r"(r[3]) : "r"(addr));
}
__device__ __forceinline__ void mma_f16(float* c, const unsigned* a, const unsigned* b) {
    asm volatile(
        "mma.sync.aligned.m16n8k16.row.col.f32.f16.f16.f32 "
        "{%0,%1,%2,%3}, {%4,%5,%6,%7}, {%8,%9}, {%0,%1,%2,%3};"
        : "+f"(c[0]), "+f"(c[1]), "+f"(c[2]), "+f"(c[3])
        : "r"(a[0]), "r"(a[1]), "r"(a[2]), "r"(a[3]), "r"(b[0]), "r"(b[1]));
}

// =====================================================================
// fp16 mma GEMM, cp.async 4-stage pipeline, ldmatrix fragments.
// C[M,N] = A[M,K] @ Bt[N,K]^T (+bias), A/Bt half, C fp32.
// CTA 128x128, BK=32 halves, 256 threads (8 warps 2x4, warp 64x32).
// Stage: A 128 rows x 64B data padded to 80B; B same. 20KB/stage, 4 stages.
// =====================================================================
#define GSTAGES   4
#define GROWB     80                        // bytes per padded row (64B data)
#define STAGE_A   (128 * GROWB)             // 10240
#define STAGE_SZ  (2 * STAGE_A)             // 20480
#define GSMEM     (GSTAGES * STAGE_SZ)      // 81920

__global__ __launch_bounds__(256, 2)
void gemm_h(const __half* __restrict__ A, const __half* __restrict__ Bt,
            const float* __restrict__ bias, float* __restrict__ C,
            int M, int N, int K)
{
    extern __shared__ char smem[];
    const uint32_t sbase = smem_u32(smem);

    const int tid  = threadIdx.x;
    const int warp = tid >> 5;
    const int lane = tid & 31;
    const int g    = lane >> 2;
    const int tg   = lane & 3;
    const int wm   = warp >> 2;     // 0..1
    const int wn   = warp & 3;      // 0..3
    const int m0   = blockIdx.y * 128;
    const int n0   = blockIdx.x * 128;

    // loader: one row per thread (A rows for tid<128, B rows for tid>=128), 4x16B
    const int lrow = tid & 127;
    const int isB  = tid >> 7;
    const __half* src = isB ? (Bt + (size_t)(n0 + lrow) * K)
                            : (A  + (size_t)(m0 + lrow) * K);
    const uint32_t dst0 = (uint32_t)(isB * STAGE_A + lrow * GROWB);
    const int KT = K / 32;

    // ldmatrix base addresses
    const int lr8  = lane & 7;
    const int rsel = (lane >> 3) & 1;
    const int ksel = (lane >> 4) & 1;
    // A: row = wm*64 + mt*16 + lr8 + rsel*8 ; k half-offset = ksel*16B
    const uint32_t a_base = sbase +
        (uint32_t)((wm * 64 + lr8 + rsel * 8) * GROWB + ksel * 16);
    // B: row = wn*32 + pr*16 + lr8 + ksel*8 ; k off = rsel*16B
    const uint32_t b_base = sbase + STAGE_A +
        (uint32_t)((wn * 32 + lr8 + ksel * 8) * GROWB + rsel * 16);

    float acc[4][4][4];
#pragma unroll
    for (int mt = 0; mt < 4; mt++)
#pragma unroll
        for (int nt = 0; nt < 4; nt++)
#pragma unroll
            for (int r = 0; r < 4; r++) acc[mt][nt][r] = 0.f;

    // prologue: stages 0..2
#pragma unroll
    for (int s = 0; s < GSTAGES - 1; s++) {
        uint32_t d = sbase + s * STAGE_SZ + dst0;
        const __half* sp = src + (size_t)s * 32;
#pragma unroll
        for (int c = 0; c < 4; c++) cp_async16(d + c * 16, sp + c * 8);
        cp_commit();
    }

    for (int kt = 0; kt < KT; kt++) {
        cp_wait<GSTAGES - 2>();
        __syncthreads();

        if (kt + GSTAGES - 1 < KT) {
            int s = (kt + GSTAGES - 1) & (GSTAGES - 1);
            uint32_t d = sbase + s * STAGE_SZ + dst0;
            const __half* sp = src + (size_t)(kt + GSTAGES - 1) * 32;
#pragma unroll
            for (int c = 0; c < 4; c++) cp_async16(d + c * 16, sp + c * 8);
        }
        cp_commit();

        const int slot = kt & (GSTAGES - 1);
        const uint32_t soff = (uint32_t)(slot * STAGE_SZ);

#pragma unroll
        for (int ks = 0; ks < 2; ks++) {
            unsigned af[4][4], bf[2][4];
#pragma unroll
            for (int mt = 0; mt < 4; mt++)
                ldm_x4(af[mt], a_base + soff + (uint32_t)(mt * 16 * GROWB + ks * 32));
#pragma unroll
            for (int pr = 0; pr < 2; pr++)
                ldm_x4(bf[pr], b_base + soff + (uint32_t)(pr * 16 * GROWB + ks * 32));
#pragma unroll
            for (int mt = 0; mt < 4; mt++)
#pragma unroll
                for (int nt = 0; nt < 4; nt++)
                    mma_f16(acc[mt][nt], af[mt], &bf[nt >> 1][(nt & 1) * 2]);
        }
    }

    // epilogue
#pragma unroll
    for (int mt = 0; mt < 4; mt++) {
        int r0 = m0 + wm * 64 + mt * 16 + g;
#pragma unroll
        for (int nt = 0; nt < 4; nt++) {
            int c = n0 + wn * 32 + nt * 8 + 2 * tg;
            float bx = 0.f, by = 0.f;
            if (bias) { bx = bias[c]; by = bias[c + 1]; }
            float2 v0 = make_float2(acc[mt][nt][0] + bx, acc[mt][nt][1] + by);
            float2 v1 = make_float2(acc[mt][nt][2] + bx, acc[mt][nt][3] + by);
            *(float2*)&C[(size_t)r0 * N + c]       = v0;
            *(float2*)&C[(size_t)(r0 + 8) * N + c] = v1;
        }
    }
}

// =====================================================================
// x -> half
// =====================================================================
__global__ __launch_bounds__(256)
void convx_kernel(const float* __restrict__ x)
{
    int i = (blockIdx.x * 256 + threadIdx.x) * 4;
    float4 v = *(const float4*)&x[i];
    __half2 p0 = __floats2half2_rn(v.x, v.y);
    __half2 p1 = __floats2half2_rn(v.z, v.w);
    *(__half2*)&g_xh[i]     = p0;
    *(__half2*)&g_xh[i + 2] = p1;
}

// =====================================================================
// transpose + half: out[C,R] = half(in[R,C]^T)
// =====================================================================
__global__ __launch_bounds__(256)
void transpose_h(const float* __restrict__ in, __half* __restrict__ out, int R, int C)
{
    __shared__ float tile[32][33];
    const int bx = blockIdx.x * 32;
    const int by = blockIdx.y * 32;
    const int x = bx + threadIdx.x;
#pragma unroll
    for (int i = threadIdx.y; i < 32; i += 8)
        tile[i][threadIdx.x] = in[(size_t)(by + i) * C + x];
    __syncthreads();
    const int ox = by + threadIdx.x;
#pragma unroll
    for (int i = threadIdx.y; i < 32; i += 8)
        out[(size_t)(bx + i) * R + ox] = __float2half(tile[threadIdx.x][i]);
}

// =====================================================================
// Multi-section RoPE
// =====================================================================
__device__ __forceinline__ int sec3(int d) {
    if (d < 16)  return 0;
    if (d < 40)  return 1;
    if (d < 64)  return 2;
    if (d < 80)  return 0;
    if (d < 104) return 1;
    return 2;
}

__global__ __launch_bounds__(64)
void rope_kernel(const float* __restrict__ cosb, const float* __restrict__ sinb,
                 float* __restrict__ out_k)
{
    const int unit = blockIdx.x;
    const int t  = unit / (N_HEADS + N_KVH);
    const int hh = unit % (N_HEADS + N_KVH);
    const int d  = threadIdx.x;
    const int d2 = d + 64;

    const float c1 = cosb[(size_t)sec3(d)  * T_SEQ * HEAD_D + (size_t)t * HEAD_D + d];
    const float s1 = sinb[(size_t)sec3(d)  * T_SEQ * HEAD_D + (size_t)t * HEAD_D + d];
    const float c2 = cosb[(size_t)sec3(d2) * T_SEQ * HEAD_D + (size_t)t * HEAD_D + d2];
    const float s2 = sinb[(size_t)sec3(d2) * T_SEQ * HEAD_D + (size_t)t * HEAD_D + d2];

    float* base;
    if (hh < N_HEADS) base = g_q + (size_t)t * C_EMB + hh * HEAD_D;
    else              base = g_k + (size_t)t * KV_W + (hh - N_HEADS) * HEAD_D;

    float x1 = base[d];
    float x2 = base[d2];
    float r1 = x1 * c1 - x2 * s1;
    float r2 = x2 * c2 + x1 * s2;
    base[d]  = r1;
    base[d2] = r2;

    if (hh >= N_HEADS) {
        int h = hh - N_HEADS;
        out_k[(size_t)h * T_SEQ * HEAD_D + (size_t)t * HEAD_D + d]  = r1;
        out_k[(size_t)h * T_SEQ * HEAD_D + (size_t)t * HEAD_D + d2] = r2;
    }
}

__global__ __launch_bounds__(256)
void vcopy_kernel(float* __restrict__ out_v)
{
    int idx = blockIdx.x * 256 + threadIdx.x;
    if (idx >= N_KVH * T_SEQ * HEAD_D) return;
    int d = idx & (HEAD_D - 1);
    int t = (idx / HEAD_D) & (T_SEQ - 1);
    int h = idx / (HEAD_D * T_SEQ);
    out_v[idx] = g_v[(size_t)t * KV_W + h * HEAD_D + d];
}

// =====================================================================
// Causal attention (two-pass tile softmax). Writes y in half.
// =====================================================================
#define AT_WARPS 16

__global__ __launch_bounds__(AT_WARPS * 32)
void attn_kernel(__half* __restrict__ Y)
{
    __shared__ float Ks[32][128];
    __shared__ float Vs[32][128];

    const int h    = blockIdx.y;
    const int kvh  = h >> 2;
    const int warp = threadIdx.x >> 5;
    const int lane = threadIdx.x & 31;
    const int t0   = blockIdx.x * AT_WARPS;
    const int t    = t0 + warp;

    const float scale = 0.08838834764831845f;

    float4 q = *(const float4*)&g_q[(size_t)t * C_EMB + h * HEAD_D + lane * 4];

    float m = -1e30f, l = 0.f;
    float4 o = make_float4(0.f, 0.f, 0.f, 0.f);

    const int tmax = t0 + AT_WARPS - 1;
    for (int kk0 = 0; kk0 <= tmax; kk0 += 32) {
        for (int i = threadIdx.x; i < 32 * 32; i += AT_WARPS * 32) {
            int row = i >> 5;
            int c4  = (i & 31) * 4;
            *(float4*)&Ks[row][c4] =
                *(const float4*)&g_k[(size_t)(kk0 + row) * KV_W + kvh * HEAD_D + c4];
            *(float4*)&Vs[row][c4] =
                *(const float4*)&g_v[(size_t)(kk0 + row) * KV_W + kvh * HEAD_D + c4];
        }
        __syncthreads();

        int jend = t - kk0 + 1;
        if (jend > 32) jend = 32;

        if (jend > 0) {
            float skeep = -1e30f;
            if (jend == 32) {
#pragma unroll
                for (int j = 0; j < 32; j++) {
                    float4 kv = *(const float4*)&Ks[j][lane * 4];
                    float s = q.x * kv.x + q.y * kv.y + q.z * kv.z + q.w * kv.w;
                    s += __shfl_xor_sync(0xffffffffu, s, 16);
                    s += __shfl_xor_sync(0xffffffffu, s, 8);
                    s += __shfl_xor_sync(0xffffffffu, s, 4);
                    s += __shfl_xor_sync(0xffffffffu, s, 2);
                    s += __shfl_xor_sync(0xffffffffu, s, 1);
                    skeep = (lane == j) ? s * scale : skeep;
                }
            } else {
                for (int j = 0; j < jend; j++) {
                    float4 kv = *(const float4*)&Ks[j][lane * 4];
                    float s = q.x * kv.x + q.y * kv.y + q.z * kv.z + q.w * kv.w;
                    s += __shfl_xor_sync(0xffffffffu, s, 16);
                    s += __shfl_xor_sync(0xffffffffu, s, 8);
                    s += __shfl_xor_sync(0xffffffffu, s, 4);
                    s += __shfl_xor_sync(0xffffffffu, s, 2);
                    s += __shfl_xor_sync(0xffffffffu, s, 1);
                    skeep = (lane == j) ? s * scale : skeep;
                }
            }

            float tm = skeep;
            tm = fmaxf(tm, __shfl_xor_sync(0xffffffffu, tm, 16));
            tm = fmaxf(tm, __shfl_xor_sync(0xffffffffu, tm, 8));
            tm = fmaxf(tm, __shfl_xor_sync(0xffffffffu, tm, 4));
            tm = fmaxf(tm, __shfl_xor_sync(0xffffffffu, tm, 2));
            tm = fmaxf(tm, __shfl_xor_sync(0xffffffffu, tm, 1));

            float mn   = fmaxf(m, tm);
            float corr = __expf(m - mn);
            float p    = __expf(skeep - mn);

            float ps = p;
            ps += __shfl_xor_sync(0xffffffffu, ps, 16);
            ps += __shfl_xor_sync(0xffffffffu, ps, 8);
            ps += __shfl_xor_sync(0xffffffffu, ps, 4);
            ps += __shfl_xor_sync(0xffffffffu, ps, 2);
            ps += __shfl_xor_sync(0xffffffffu, ps, 1);

            l = l * corr + ps;
            o.x *= corr; o.y *= corr; o.z *= corr; o.w *= corr;
            m = mn;

            if (jend == 32) {
#pragma unroll
                for (int j = 0; j < 32; j++) {
                    float pj = __shfl_sync(0xffffffffu, p, j);
                    float4 vv = *(const float4*)&Vs[j][lane * 4];
                    o.x += pj * vv.x; o.y += pj * vv.y;
                    o.z += pj * vv.z; o.w += pj * vv.w;
                }
            } else {
                for (int j = 0; j < jend; j++) {
                    float pj = __shfl_sync(0xffffffffu, p, j);
                    float4 vv = *(const float4*)&Vs[j][lane * 4];
                    o.x += pj * vv.x; o.y += pj * vv.y;
                    o.z += pj * vv.z; o.w += pj * vv.w;
                }
            }
        }
        __syncthreads();
    }

    float inv = 1.f / l;
    __half* yo = &Y[(size_t)t * C_EMB + h * HEAD_D + lane * 4];
    yo[0] = __float2half(o.x * inv);
    yo[1] = __float2half(o.y * inv);
    yo[2] = __float2half(o.z * inv);
    yo[3] = __float2half(o.w * inv);
}

// =====================================================================
// launch
// =====================================================================
extern "C" void kernel_launch(void* const* d_in, const int* in_sizes, int n_in,
                              void* d_out, int out_size)
{
    (void)in_sizes; (void)n_in; (void)out_size;
    const float* x    = (const float*)d_in[0];
    const float* cosb = (const float*)d_in[1];
    const float* sinb = (const float*)d_in[2];
    const float* Wq   = (const float*)d_in[3];
    const float* bq   = (const float*)d_in[4];
    const float* Wk   = (const float*)d_in[5];
    const float* bk   = (const float*)d_in[6];
    const float* Wv   = (const float*)d_in[7];
    const float* bv   = (const float*)d_in[8];
    const float* Wo   = (const float*)d_in[9];

    float* out   = (float*)d_out;
    float* out_y = out;
    float* out_k = out + (size_t)T_SEQ * C_EMB;
    float* out_v = out_k + (size_t)N_KVH * T_SEQ * HEAD_D;

    float*  qb;  cudaGetSymbolAddress((void**)&qb,  g_q);
    float*  kb;  cudaGetSymbolAddress((void**)&kb,  g_k);
    float*  vb;  cudaGetSymbolAddress((void**)&vb,  g_v);
    __half* yhb; cudaGetSymbolAddress((void**)&yhb, g_yh);
    __half* xhb; cudaGetSymbolAddress((void**)&xhb, g_xh);
    __half* wqt; cudaGetSymbolAddress((void**)&wqt, g_wqt);
    __half* wkt; cudaGetSymbolAddress((void**)&wkt, g_wkt);
    __half* wvt; cudaGetSymbolAddress((void**)&wvt, g_wvt);
    __half* wot; cudaGetSymbolAddress((void**)&wot, g_wot);

    cudaFuncSetAttribute(gemm_h, cudaFuncAttributeMaxDynamicSharedMemorySize, GSMEM);

    // 1: x -> half
    convx_kernel<<<(T_SEQ * C_EMB / 4) / 256, 256>>>(x);

    // 2-5: weight transposes (+half)
    {
        dim3 blk(32, 8);
        transpose_h<<<dim3(C_EMB / 32, C_EMB / 32), blk>>>(Wq, wqt, C_EMB, C_EMB);
        transpose_h<<<dim3(KV_W / 32, C_EMB / 32), blk>>>(Wk, wkt, C_EMB, KV_W);
        transpose_h<<<dim3(KV_W / 32, C_EMB / 32), blk>>>(Wv, wvt, C_EMB, KV_W);
        transpose_h<<<dim3(C_EMB / 32, C_EMB / 32), blk>>>(Wo, wot, C_EMB, C_EMB);
    }

    // 6-8: QKV projections (fp16 mma)  [launch 6 = gemmQ is the ncu-captured one]
    gemm_h<<<dim3(C_EMB / 128, T_SEQ / 128), 256, GSMEM>>>(xhb, wqt, bq, qb, T_SEQ, C_EMB, C_EMB);
    gemm_h<<<dim3(KV_W / 128, T_SEQ / 128), 256, GSMEM>>>(xhb, wkt, bk, kb, T_SEQ, KV_W, C_EMB);
    gemm_h<<<dim3(KV_W / 128, T_SEQ / 128), 256, GSMEM>>>(xhb, wvt, bv, vb, T_SEQ, KV_W, C_EMB);

    // 9: RoPE (also writes present_k)
    rope_kernel<<<T_SEQ * (N_HEADS + N_KVH), 64>>>(cosb, sinb, out_k);

    // 10: present_v
    vcopy_kernel<<<(N_KVH * T_SEQ * HEAD_D + 255) / 256, 256>>>(out_v);

    // 11: causal attention (writes half y)
    attn_kernel<<<dim3(T_SEQ / AT_WARPS, N_HEADS), AT_WARPS * 32>>>(yhb);

    // 12: output projection
    gemm_h<<<dim3(C_EMB / 128, T_SEQ / 128), 256, GSMEM>>>(yhb, wot, nullptr, out_y, T_SEQ, C_EMB, C_EMB);
}

// round 7
// speedup vs baseline: 2.7458x; 1.9198x over previous
#include <cuda_runtime.h>
#include <cuda_fp16.h>
#include <math.h>
#include <cstdint>

// Problem constants
#define T_SEQ   2048
#define C_EMB   2048
#define N_HEADS 16
#define N_KVH   4
#define HEAD_D  128
#define KV_W    (N_KVH * HEAD_D)   // 512

// -------- scratch (device globals; no allocation allowed) --------
__device__ float  g_q[T_SEQ * C_EMB];
__device__ float  g_k[T_SEQ * KV_W];
__device__ float  g_v[T_SEQ * KV_W];
__device__ __half g_yh[T_SEQ * C_EMB];      // attention out (half, for final gemm)
__device__ __half g_xh[T_SEQ * C_EMB];      // x in half
// transposed weights [N, K] row-major (K contiguous), half
__device__ __half g_wqt[C_EMB * C_EMB];
__device__ __half g_wkt[KV_W * C_EMB];
__device__ __half g_wvt[KV_W * C_EMB];
__device__ __half g_wot[C_EMB * C_EMB];

// =====================================================================
// helpers
// =====================================================================
__device__ __forceinline__ uint32_t smem_u32(const void* p) {
    uint32_t a;
    asm("{ .reg .u64 t; cvta.to.shared.u64 t, %1; cvt.u32.u64 %0, t; }" : "=r"(a) : "l"(p));
    return a;
}
__device__ __forceinline__ void cp_async16(uint32_t dst, const void* src) {
    asm volatile("cp.async.ca.shared.global [%0], [%1], 16;" :: "r"(dst), "l"(src) : "memory");
}
__device__ __forceinline__ void cp_commit() {
    asm volatile("cp.async.commit_group;" ::: "memory");
}
template <int N>
__device__ __forceinline__ void cp_wait() {
    asm volatile("cp.async.wait_group %0;" :: "n"(N) : "memory");
}
__device__ __forceinline__ void ldm_x4(unsigned* r, uint32_t addr) {
    asm volatile("ldmatrix.sync.aligned.m8n8.x4.shared.b16 {%0,%1,%2,%3}, [%4];"
        : "=r"(r[0]), "=r"(r[1]), "=r"(r[2]), "=r"(r[3]) : "r"(addr));
}
__device__ __forceinline__ void mma_f16(float* c, const unsigned* a, const unsigned* b) {
    asm volatile(
        "mma.sync.aligned.m16n8k16.row.col.f32.f16.f16.f32 "
        "{%0,%1,%2,%3}, {%4,%5,%6,%7}, {%8,%9}, {%0,%1,%2,%3};"
        : "+f"(c[0]), "+f"(c[1]), "+f"(c[2]), "+f"(c[3])
        : "r"(a[0]), "r"(a[1]), "r"(a[2]), "r"(a[3]), "r"(b[0]), "r"(b[1]));
}

// =====================================================================
// fp16 mma GEMM (unchanged from R6 — passing, rel_err 4.5e-4)
// =====================================================================
#define GSTAGES   4
#define GROWB     80
#define STAGE_A   (128 * GROWB)
#define STAGE_SZ  (2 * STAGE_A)
#define GSMEM     (GSTAGES * STAGE_SZ)

__global__ __launch_bounds__(256, 2)
void gemm_h(const __half* __restrict__ A, const __half* __restrict__ Bt,
            const float* __restrict__ bias, float* __restrict__ C,
            int M, int N, int K)
{
    extern __shared__ char smem[];
    const uint32_t sbase = smem_u32(smem);

    const int tid  = threadIdx.x;
    const int warp = tid >> 5;
    const int lane = tid & 31;
    const int g    = lane >> 2;
    const int tg   = lane & 3;
    const int wm   = warp >> 2;
    const int wn   = warp & 3;
    const int m0   = blockIdx.y * 128;
    const int n0   = blockIdx.x * 128;

    const int lrow = tid & 127;
    const int isB  = tid >> 7;
    const __half* src = isB ? (Bt + (size_t)(n0 + lrow) * K)
                            : (A  + (size_t)(m0 + lrow) * K);
    const uint32_t dst0 = (uint32_t)(isB * STAGE_A + lrow * GROWB);
    const int KT = K / 32;

    const int lr8  = lane & 7;
    const int rsel = (lane >> 3) & 1;
    const int ksel = (lane >> 4) & 1;
    const uint32_t a_base = sbase +
        (uint32_t)((wm * 64 + lr8 + rsel * 8) * GROWB + ksel * 16);
    const uint32_t b_base = sbase + STAGE_A +
        (uint32_t)((wn * 32 + lr8 + ksel * 8) * GROWB + rsel * 16);

    float acc[4][4][4];
#pragma unroll
    for (int mt = 0; mt < 4; mt++)
#pragma unroll
        for (int nt = 0; nt < 4; nt++)
#pragma unroll
            for (int r = 0; r < 4; r++) acc[mt][nt][r] = 0.f;

#pragma unroll
    for (int s = 0; s < GSTAGES - 1; s++) {
        uint32_t d = sbase + s * STAGE_SZ + dst0;
        const __half* sp = src + (size_t)s * 32;
#pragma unroll
        for (int c = 0; c < 4; c++) cp_async16(d + c * 16, sp + c * 8);
        cp_commit();
    }

    for (int kt = 0; kt < KT; kt++) {
        cp_wait<GSTAGES - 2>();
        __syncthreads();

        if (kt + GSTAGES - 1 < KT) {
            int s = (kt + GSTAGES - 1) & (GSTAGES - 1);
            uint32_t d = sbase + s * STAGE_SZ + dst0;
            const __half* sp = src + (size_t)(kt + GSTAGES - 1) * 32;
#pragma unroll
            for (int c = 0; c < 4; c++) cp_async16(d + c * 16, sp + c * 8);
        }
        cp_commit();

        const int slot = kt & (GSTAGES - 1);
        const uint32_t soff = (uint32_t)(slot * STAGE_SZ);

#pragma unroll
        for (int ks = 0; ks < 2; ks++) {
            unsigned af[4][4], bf[2][4];
#pragma unroll
            for (int mt = 0; mt < 4; mt++)
                ldm_x4(af[mt], a_base + soff + (uint32_t)(mt * 16 * GROWB + ks * 32));
#pragma unroll
            for (int pr = 0; pr < 2; pr++)
                ldm_x4(bf[pr], b_base + soff + (uint32_t)(pr * 16 * GROWB + ks * 32));
#pragma unroll
            for (int mt = 0; mt < 4; mt++)
#pragma unroll
                for (int nt = 0; nt < 4; nt++)
                    mma_f16(acc[mt][nt], af[mt], &bf[nt >> 1][(nt & 1) * 2]);
        }
    }

#pragma unroll
    for (int mt = 0; mt < 4; mt++) {
        int r0 = m0 + wm * 64 + mt * 16 + g;
#pragma unroll
        for (int nt = 0; nt < 4; nt++) {
            int c = n0 + wn * 32 + nt * 8 + 2 * tg;
            float bx = 0.f, by = 0.f;
            if (bias) { bx = bias[c]; by = bias[c + 1]; }
            float2 v0 = make_float2(acc[mt][nt][0] + bx, acc[mt][nt][1] + by);
            float2 v1 = make_float2(acc[mt][nt][2] + bx, acc[mt][nt][3] + by);
            *(float2*)&C[(size_t)r0 * N + c]       = v0;
            *(float2*)&C[(size_t)(r0 + 8) * N + c] = v1;
        }
    }
}

// =====================================================================
// x -> half
// =====================================================================
__global__ __launch_bounds__(256)
void convx_kernel(const float* __restrict__ x)
{
    int i = (blockIdx.x * 256 + threadIdx.x) * 4;
    float4 v = *(const float4*)&x[i];
    *(__half2*)&g_xh[i]     = __floats2half2_rn(v.x, v.y);
    *(__half2*)&g_xh[i + 2] = __floats2half2_rn(v.z, v.w);
}

// =====================================================================
// fused transpose of all 4 weights (one launch): out[C,R] = half(in^T)
// =====================================================================
__global__ __launch_bounds__(256)
void transpose_all(const float* __restrict__ Wq, const float* __restrict__ Wk,
                   const float* __restrict__ Wv, const float* __restrict__ Wo)
{
    __shared__ float tile[32][33];
    const int z = blockIdx.z;
    const float* in;
    __half* out;
    int C;
    if (z == 0)      { in = Wq; out = g_wqt; C = C_EMB; }
    else if (z == 1) { in = Wk; out = g_wkt; C = KV_W; }
    else if (z == 2) { in = Wv; out = g_wvt; C = KV_W; }
    else             { in = Wo; out = g_wot; C = C_EMB; }
    const int bx = blockIdx.x * 32;
    if (bx >= C) return;
    const int by = blockIdx.y * 32;
    const int R = C_EMB;
    const int x = bx + threadIdx.x;
#pragma unroll
    for (int i = threadIdx.y; i < 32; i += 8)
        tile[i][threadIdx.x] = in[(size_t)(by + i) * C + x];
    __syncthreads();
    const int ox = by + threadIdx.x;
#pragma unroll
    for (int i = threadIdx.y; i < 32; i += 8)
        out[(size_t)(bx + i) * R + ox] = __float2half(tile[threadIdx.x][i]);
}

// =====================================================================
// Multi-section RoPE
// =====================================================================
__device__ __forceinline__ int sec3(int d) {
    if (d < 16)  return 0;
    if (d < 40)  return 1;
    if (d < 64)  return 2;
    if (d < 80)  return 0;
    if (d < 104) return 1;
    return 2;
}

__global__ __launch_bounds__(64)
void rope_kernel(const float* __restrict__ cosb, const float* __restrict__ sinb,
                 float* __restrict__ out_k)
{
    const int unit = blockIdx.x;
    const int t  = unit / (N_HEADS + N_KVH);
    const int hh = unit % (N_HEADS + N_KVH);
    const int d  = threadIdx.x;
    const int d2 = d + 64;

    const float c1 = cosb[(size_t)sec3(d)  * T_SEQ * HEAD_D + (size_t)t * HEAD_D + d];
    const float s1 = sinb[(size_t)sec3(d)  * T_SEQ * HEAD_D + (size_t)t * HEAD_D + d];
    const float c2 = cosb[(size_t)sec3(d2) * T_SEQ * HEAD_D + (size_t)t * HEAD_D + d2];
    const float s2 = sinb[(size_t)sec3(d2) * T_SEQ * HEAD_D + (size_t)t * HEAD_D + d2];

    float* base;
    if (hh < N_HEADS) base = g_q + (size_t)t * C_EMB + hh * HEAD_D;
    else              base = g_k + (size_t)t * KV_W + (hh - N_HEADS) * HEAD_D;

    float x1 = base[d];
    float x2 = base[d2];
    float r1 = x1 * c1 - x2 * s1;
    float r2 = x2 * c2 + x1 * s2;
    base[d]  = r1;
    base[d2] = r2;

    if (hh >= N_HEADS) {
        int h = hh - N_HEADS;
        out_k[(size_t)h * T_SEQ * HEAD_D + (size_t)t * HEAD_D + d]  = r1;
        out_k[(size_t)h * T_SEQ * HEAD_D + (size_t)t * HEAD_D + d2] = r2;
    }
}

__global__ __launch_bounds__(256)
void vcopy_kernel(float* __restrict__ out_v)
{
    int idx = blockIdx.x * 256 + threadIdx.x;
    if (idx >= N_KVH * T_SEQ * HEAD_D) return;
    int d = idx & (HEAD_D - 1);
    int t = (idx / HEAD_D) & (T_SEQ - 1);
    int h = idx / (HEAD_D * T_SEQ);
    out_v[idx] = g_v[(size_t)t * KV_W + h * HEAD_D + d];
}

// =====================================================================
// Causal attention — lane-owns-key, 8 q-rows per warp, f32x2 math.
// Block: 256 threads (8 warps), 64 q rows per block, one head.
// Lane j of a warp owns key (kk0 + j): computes the full 128-d dot for
// its key against all 8 of the warp's q rows (Q broadcast from smem).
// No shfl in score computation; softmax uses 10 shfl per row per tile;
// PV broadcasts p one key at a time (1 shfl per key per row).
// Accumulation uses packed fma.rn.f32x2 (2x the FFMA pipe).
// =====================================================================
#define AKPAD 132                           // K/V row stride (words): +4 banks/row
#define ATT_SMEM (64*128*4 + 2*32*AKPAD*4)  // 32768 + 2*16896 = 66560

__global__ __launch_bounds__(256, 2)
void attn_kernel(__half* __restrict__ Y)
{
    extern __shared__ float sm[];
    float* Qs = sm;                         // [64][128]
    float* Ks = sm + 64 * 128;              // [32][AKPAD]
    float* Vs = Ks + 32 * AKPAD;            // [32][AKPAD]
    const uint32_t qs_base = smem_u32(Qs);
    const uint32_t ks_base = smem_u32(Ks);
    const uint32_t vs_base = smem_u32(Vs);

    const int h    = blockIdx.y;
    const int kvh  = h >> 2;
    const int t0   = blockIdx.x * 64;
    const int tid  = threadIdx.x;
    const int warp = tid >> 5;
    const int lane = tid & 31;
    const int wrow0 = t0 + warp * 8;

    // load Q tile [64 rows x 128]
    for (int i = tid; i < 64 * 32; i += 256) {
        int row = i >> 5, c4 = (i & 31) * 4;
        *(float4*)&Qs[row * 128 + c4] =
            *(const float4*)&g_q[(size_t)(t0 + row) * C_EMB + h * HEAD_D + c4];
    }

    unsigned long long o2[8][2];
    float m[8], l[8], p[8];
#pragma unroll
    for (int r = 0; r < 8; r++) { o2[r][0] = 0ull; o2[r][1] = 0ull; m[r] = -1e30f; l[r] = 0.f; }

    const float scale = 0.08838834764831845f;
    const uint32_t ka0 = ks_base + (uint32_t)lane * (AKPAD * 4);
    const uint32_t va0 = vs_base + (uint32_t)lane * 16;
    const uint32_t qa0 = qs_base + (uint32_t)(warp * 8) * 512;

    const int kend = t0 + 64;
    for (int kk0 = 0; kk0 < kend; kk0 += 32) {
        __syncthreads();
        // cooperative K/V tile load (32 keys x 128)
        for (int i = tid; i < 32 * 32; i += 256) {
            int row = i >> 5, c4 = (i & 31) * 4;
            *(float4*)&Ks[row * AKPAD + c4] =
                *(const float4*)&g_k[(size_t)(kk0 + row) * KV_W + kvh * HEAD_D + c4];
            *(float4*)&Vs[row * AKPAD + c4] =
                *(const float4*)&g_v[(size_t)(kk0 + row) * KV_W + kvh * HEAD_D + c4];
        }
        __syncthreads();

        if (kk0 > wrow0 + 7) continue;   // warp-uniform skip (all warps still sync)

        // ---- scores: lane owns key kk0+lane, f32x2 dot over 128 d ----
        unsigned long long sa[8], sb[8];
#pragma unroll
        for (int r = 0; r < 8; r++) { sa[r] = 0ull; sb[r] = 0ull; }

#pragma unroll 4
        for (int d4 = 0; d4 < 32; d4++) {
            unsigned long long k01, k23;
            asm("ld.shared.v2.u64 {%0,%1}, [%2];"
                : "=l"(k01), "=l"(k23) : "r"(ka0 + (uint32_t)(d4 * 16)));
#pragma unroll
            for (int r = 0; r < 8; r++) {
                unsigned long long q01, q23;
                asm("ld.shared.v2.u64 {%0,%1}, [%2];"
                    : "=l"(q01), "=l"(q23) : "r"(qa0 + (uint32_t)(r * 512 + d4 * 16)));
                asm("fma.rn.f32x2 %0, %1, %2, %0;" : "+l"(sa[r]) : "l"(q01), "l"(k01));
                asm("fma.rn.f32x2 %0, %1, %2, %0;" : "+l"(sb[r]) : "l"(q23), "l"(k23));
            }
        }

        const int kglob = kk0 + lane;
#pragma unroll
        for (int r = 0; r < 8; r++) {
            float x0, x1, x2, x3;
            asm("mov.b64 {%0,%1}, %2;" : "=f"(x0), "=f"(x1) : "l"(sa[r]));
            asm("mov.b64 {%0,%1}, %2;" : "=f"(x2), "=f"(x3) : "l"(sb[r]));
            float s = (x0 + x1) + (x2 + x3);
            s = (kglob <= wrow0 + r) ? s * scale : -1e30f;

            float tm = s;
            tm = fmaxf(tm, __shfl_xor_sync(0xffffffffu, tm, 16));
            tm = fmaxf(tm, __shfl_xor_sync(0xffffffffu, tm, 8));
            tm = fmaxf(tm, __shfl_xor_sync(0xffffffffu, tm, 4));
            tm = fmaxf(tm, __shfl_xor_sync(0xffffffffu, tm, 2));
            tm = fmaxf(tm, __shfl_xor_sync(0xffffffffu, tm, 1));

            float mn   = fmaxf(m[r], tm);
            float corr = __expf(m[r] - mn);
            float pv   = __expf(s - mn);

            float ps = pv;
            ps += __shfl_xor_sync(0xffffffffu, ps, 16);
            ps += __shfl_xor_sync(0xffffffffu, ps, 8);
            ps += __shfl_xor_sync(0xffffffffu, ps, 4);
            ps += __shfl_xor_sync(0xffffffffu, ps, 2);
            ps += __shfl_xor_sync(0xffffffffu, ps, 1);

            l[r] = l[r] * corr + ps;
            m[r] = mn;
            p[r] = pv;

            unsigned long long c2;
            asm("mov.b64 %0, {%1,%1};" : "=l"(c2) : "f"(corr));
            asm("mul.rn.f32x2 %0, %0, %1;" : "+l"(o2[r][0]) : "l"(c2));
            asm("mul.rn.f32x2 %0, %0, %1;" : "+l"(o2[r][1]) : "l"(c2));
        }

        // ---- PV: broadcast p per key, accumulate V (lane owns d-slice) ----
#pragma unroll 4
        for (int j = 0; j < 32; j++) {
            unsigned long long v01, v23;
            asm("ld.shared.v2.u64 {%0,%1}, [%2];"
                : "=l"(v01), "=l"(v23) : "r"(va0 + (uint32_t)(j * AKPAD * 4)));
#pragma unroll
            for (int r = 0; r < 8; r++) {
                float pj = __shfl_sync(0xffffffffu, p[r], j);
                unsigned long long p2;
                asm("mov.b64 %0, {%1,%1};" : "=l"(p2) : "f"(pj));
                asm("fma.rn.f32x2 %0, %1, %2, %0;" : "+l"(o2[r][0]) : "l"(p2), "l"(v01));
                asm("fma.rn.f32x2 %0, %1, %2, %0;" : "+l"(o2[r][1]) : "l"(p2), "l"(v23));
            }
        }
    }

    // epilogue: normalize + write half
#pragma unroll
    for (int r = 0; r < 8; r++) {
        float inv = 1.f / l[r];
        float x0, x1, x2, x3;
        asm("mov.b64 {%0,%1}, %2;" : "=f"(x0), "=f"(x1) : "l"(o2[r][0]));
        asm("mov.b64 {%0,%1}, %2;" : "=f"(x2), "=f"(x3) : "l"(o2[r][1]));
        __half2 h0 = __floats2half2_rn(x0 * inv, x1 * inv);
        __half2 h1 = __floats2half2_rn(x2 * inv, x3 * inv);
        uint2 u;
        u.x = *reinterpret_cast<unsigned*>(&h0);
        u.y = *reinterpret_cast<unsigned*>(&h1);
        *(uint2*)&Y[(size_t)(wrow0 + r) * C_EMB + h * HEAD_D + lane * 4] = u;
    }
}

// =====================================================================
// launch
// =====================================================================
extern "C" void kernel_launch(void* const* d_in, const int* in_sizes, int n_in,
                              void* d_out, int out_size)
{
    (void)in_sizes; (void)n_in; (void)out_size;
    const float* x    = (const float*)d_in[0];
    const float* cosb = (const float*)d_in[1];
    const float* sinb = (const float*)d_in[2];
    const float* Wq   = (const float*)d_in[3];
    const float* bq   = (const float*)d_in[4];
    const float* Wk   = (const float*)d_in[5];
    const float* bk   = (const float*)d_in[6];
    const float* Wv   = (const float*)d_in[7];
    const float* bv   = (const float*)d_in[8];
    const float* Wo   = (const float*)d_in[9];

    float* out   = (float*)d_out;
    float* out_y = out;
    float* out_k = out + (size_t)T_SEQ * C_EMB;
    float* out_v = out_k + (size_t)N_KVH * T_SEQ * HEAD_D;

    float*  qb;  cudaGetSymbolAddress((void**)&qb,  g_q);
    float*  kb;  cudaGetSymbolAddress((void**)&kb,  g_k);
    float*  vb;  cudaGetSymbolAddress((void**)&vb,  g_v);
    __half* yhb; cudaGetSymbolAddress((void**)&yhb, g_yh);
    __half* xhb; cudaGetSymbolAddress((void**)&xhb, g_xh);
    __half* wqt; cudaGetSymbolAddress((void**)&wqt, g_wqt);
    __half* wkt; cudaGetSymbolAddress((void**)&wkt, g_wkt);
    __half* wvt; cudaGetSymbolAddress((void**)&wvt, g_wvt);
    __half* wot; cudaGetSymbolAddress((void**)&wot, g_wot);

    cudaFuncSetAttribute(gemm_h, cudaFuncAttributeMaxDynamicSharedMemorySize, GSMEM);
    cudaFuncSetAttribute(attn_kernel, cudaFuncAttributeMaxDynamicSharedMemorySize, ATT_SMEM);

    // 1: fused weight transposes (+half)
    transpose_all<<<dim3(64, 64, 4), dim3(32, 8)>>>(Wq, Wk, Wv, Wo);

    // 2: x -> half
    convx_kernel<<<(T_SEQ * C_EMB / 4) / 256, 256>>>(x);

    // 3-4: K, V projections
    gemm_h<<<dim3(KV_W / 128, T_SEQ / 128), 256, GSMEM>>>(xhb, wkt, bk, kb, T_SEQ, KV_W, C_EMB);
    gemm_h<<<dim3(KV_W / 128, T_SEQ / 128), 256, GSMEM>>>(xhb, wvt, bv, vb, T_SEQ, KV_W, C_EMB);

    // 5: Q projection  (my 5th launch = the ncu-captured one)
    gemm_h<<<dim3(C_EMB / 128, T_SEQ / 128), 256, GSMEM>>>(xhb, wqt, bq, qb, T_SEQ, C_EMB, C_EMB);

    // 6: RoPE (also writes present_k)
    rope_kernel<<<T_SEQ * (N_HEADS + N_KVH), 64>>>(cosb, sinb, out_k);

    // 7: present_v
    vcopy_kernel<<<(N_KVH * T_SEQ * HEAD_D + 255) / 256, 256>>>(out_v);

    // 8: causal attention (writes half y)
    attn_kernel<<<dim3(T_SEQ / 64, N_HEADS), 256, ATT_SMEM>>>(yhb);

    // 9: output projection
    gemm_h<<<dim3(C_EMB / 128, T_SEQ / 128), 256, GSMEM>>>(yhb, wot, nullptr, out_y, T_SEQ, C_EMB, C_EMB);
}

// round 8
// speedup vs baseline: 6.1933x; 2.2556x over previous
#include <cuda_runtime.h>
#include <cuda_fp16.h>
#include <math.h>
#include <cstdint>

// Problem constants
#define T_SEQ   2048
#define C_EMB   2048
#define N_HEADS 16
#define N_KVH   4
#define HEAD_D  128
#define KV_W    (N_KVH * HEAD_D)   // 512
#define QKV_W   (C_EMB + 2 * KV_W) // 3072

// -------- scratch (device globals; no allocation allowed) --------
__device__ float  g_qkv[T_SEQ * QKV_W];     // fused QKV output [T, 3072]
__device__ __half g_yh[T_SEQ * C_EMB];      // attention out (half)
__device__ __half g_xh[T_SEQ * C_EMB];      // x in half
__device__ __half g_wqkvt[QKV_W * C_EMB];   // concat transposed weights [3072, 2048]
__device__ __half g_wot[C_EMB * C_EMB];
__device__ float  g_bqkv[QKV_W];            // concat bias

// =====================================================================
// helpers
// =====================================================================
__device__ __forceinline__ uint32_t smem_u32(const void* p) {
    uint32_t a;
    asm("{ .reg .u64 t; cvta.to.shared.u64 t, %1; cvt.u32.u64 %0, t; }" : "=r"(a) : "l"(p));
    return a;
}
__device__ __forceinline__ void cp_async16(uint32_t dst, const void* src) {
    asm volatile("cp.async.ca.shared.global [%0], [%1], 16;" :: "r"(dst), "l"(src) : "memory");
}
__device__ __forceinline__ void cp_commit() {
    asm volatile("cp.async.commit_group;" ::: "memory");
}
template <int N>
__device__ __forceinline__ void cp_wait() {
    asm volatile("cp.async.wait_group %0;" :: "n"(N) : "memory");
}
__device__ __forceinline__ void ldm_x4(unsigned* r, uint32_t addr) {
    asm volatile("ldmatrix.sync.aligned.m8n8.x4.shared.b16 {%0,%1,%2,%3}, [%4];"
        : "=r"(r[0]), "=r"(r[1]), "=r"(r[2]), "=r"(r[3]) : "r"(addr));
}
__device__ __forceinline__ void mma_f16(float* c, const unsigned* a, const unsigned* b) {
    asm volatile(
        "mma.sync.aligned.m16n8k16.row.col.f32.f16.f16.f32 "
        "{%0,%1,%2,%3}, {%4,%5,%6,%7}, {%8,%9}, {%0,%1,%2,%3};"
        : "+f"(c[0]), "+f"(c[1]), "+f"(c[2]), "+f"(c[3])
        : "r"(a[0]), "r"(a[1]), "r"(a[2]), "r"(a[3]), "r"(b[0]), "r"(b[1]));
}
__device__ __forceinline__ unsigned pack_h2(float a, float b) {
    __half2 h = __floats2half2_rn(a, b);
    return *reinterpret_cast<unsigned*>(&h);
}

// =====================================================================
// fp16 mma GEMM (validated in R6/R7)
// =====================================================================
#define GSTAGES   4
#define GROWB     80
#define STAGE_A   (128 * GROWB)
#define STAGE_SZ  (2 * STAGE_A)
#define GSMEM     (GSTAGES * STAGE_SZ)

__global__ __launch_bounds__(256, 2)
void gemm_h(const __half* __restrict__ A, const __half* __restrict__ Bt,
            const float* __restrict__ bias, float* __restrict__ C,
            int M, int N, int K)
{
    extern __shared__ char smem[];
    const uint32_t sbase = smem_u32(smem);

    const int tid  = threadIdx.x;
    const int warp = tid >> 5;
    const int lane = tid & 31;
    const int g    = lane >> 2;
    const int tg   = lane & 3;
    const int wm   = warp >> 2;
    const int wn   = warp & 3;
    const int m0   = blockIdx.y * 128;
    const int n0   = blockIdx.x * 128;

    const int lrow = tid & 127;
    const int isB  = tid >> 7;
    const __half* src = isB ? (Bt + (size_t)(n0 + lrow) * K)
                            : (A  + (size_t)(m0 + lrow) * K);
    const uint32_t dst0 = (uint32_t)(isB * STAGE_A + lrow * GROWB);
    const int KT = K / 32;

    const int lr8  = lane & 7;
    const int rsel = (lane >> 3) & 1;
    const int ksel = (lane >> 4) & 1;
    const uint32_t a_base = sbase +
        (uint32_t)((wm * 64 + lr8 + rsel * 8) * GROWB + ksel * 16);
    const uint32_t b_base = sbase + STAGE_A +
        (uint32_t)((wn * 32 + lr8 + ksel * 8) * GROWB + rsel * 16);

    float acc[4][4][4];
#pragma unroll
    for (int mt = 0; mt < 4; mt++)
#pragma unroll
        for (int nt = 0; nt < 4; nt++)
#pragma unroll
            for (int r = 0; r < 4; r++) acc[mt][nt][r] = 0.f;

#pragma unroll
    for (int s = 0; s < GSTAGES - 1; s++) {
        uint32_t d = sbase + s * STAGE_SZ + dst0;
        const __half* sp = src + (size_t)s * 32;
#pragma unroll
        for (int c = 0; c < 4; c++) cp_async16(d + c * 16, sp + c * 8);
        cp_commit();
    }

    for (int kt = 0; kt < KT; kt++) {
        cp_wait<GSTAGES - 2>();
        __syncthreads();

        if (kt + GSTAGES - 1 < KT) {
            int s = (kt + GSTAGES - 1) & (GSTAGES - 1);
            uint32_t d = sbase + s * STAGE_SZ + dst0;
            const __half* sp = src + (size_t)(kt + GSTAGES - 1) * 32;
#pragma unroll
            for (int c = 0; c < 4; c++) cp_async16(d + c * 16, sp + c * 8);
        }
        cp_commit();

        const int slot = kt & (GSTAGES - 1);
        const uint32_t soff = (uint32_t)(slot * STAGE_SZ);

#pragma unroll
        for (int ks = 0; ks < 2; ks++) {
            unsigned af[4][4], bf[2][4];
#pragma unroll
            for (int mt = 0; mt < 4; mt++)
                ldm_x4(af[mt], a_base + soff + (uint32_t)(mt * 16 * GROWB + ks * 32));
#pragma unroll
            for (int pr = 0; pr < 2; pr++)
                ldm_x4(bf[pr], b_base + soff + (uint32_t)(pr * 16 * GROWB + ks * 32));
#pragma unroll
            for (int mt = 0; mt < 4; mt++)
#pragma unroll
                for (int nt = 0; nt < 4; nt++)
                    mma_f16(acc[mt][nt], af[mt], &bf[nt >> 1][(nt & 1) * 2]);
        }
    }

#pragma unroll
    for (int mt = 0; mt < 4; mt++) {
        int r0 = m0 + wm * 64 + mt * 16 + g;
#pragma unroll
        for (int nt = 0; nt < 4; nt++) {
            int c = n0 + wn * 32 + nt * 8 + 2 * tg;
            float bx = 0.f, by = 0.f;
            if (bias) { bx = bias[c]; by = bias[c + 1]; }
            float2 v0 = make_float2(acc[mt][nt][0] + bx, acc[mt][nt][1] + by);
            float2 v1 = make_float2(acc[mt][nt][2] + bx, acc[mt][nt][3] + by);
            *(float2*)&C[(size_t)r0 * N + c]       = v0;
            *(float2*)&C[(size_t)(r0 + 8) * N + c] = v1;
        }
    }
}

// =====================================================================
// x -> half
// =====================================================================
__global__ __launch_bounds__(256)
void convx_kernel(const float* __restrict__ x)
{
    int i = (blockIdx.x * 256 + threadIdx.x) * 4;
    float4 v = *(const float4*)&x[i];
    *(__half2*)&g_xh[i]     = __floats2half2_rn(v.x, v.y);
    *(__half2*)&g_xh[i + 2] = __floats2half2_rn(v.z, v.w);
}

// =====================================================================
// fused transpose of weights into g_wqkvt / g_wot, + bias concat (z==4)
// =====================================================================
__global__ __launch_bounds__(256)
void transpose_all(const float* __restrict__ Wq, const float* __restrict__ Wk,
                   const float* __restrict__ Wv, const float* __restrict__ Wo,
                   const float* __restrict__ bq, const float* __restrict__ bk,
                   const float* __restrict__ bv)
{
    const int z = blockIdx.z;
    if (z == 4) {
        if (blockIdx.y == 0 && blockIdx.x < 12) {
            int idx = blockIdx.x * 256 + threadIdx.y * 32 + threadIdx.x;
            float v = (idx < 2048) ? bq[idx]
                    : (idx < 2560) ? bk[idx - 2048]
                                   : bv[idx - 2560];
            g_bqkv[idx] = v;
        }
        return;
    }
    __shared__ float tile[32][33];
    const float* in;
    __half* out;
    int C;
    if (z == 0)      { in = Wq; out = g_wqkvt;               C = C_EMB; }
    else if (z == 1) { in = Wk; out = g_wqkvt + 2048 * 2048; C = KV_W; }
    else if (z == 2) { in = Wv; out = g_wqkvt + 2560 * 2048; C = KV_W; }
    else             { in = Wo; out = g_wot;                 C = C_EMB; }
    const int bx = blockIdx.x * 32;
    if (bx >= C) return;
    const int by = blockIdx.y * 32;
    const int R = C_EMB;
    const int x = bx + threadIdx.x;
#pragma unroll
    for (int i = threadIdx.y; i < 32; i += 8)
        tile[i][threadIdx.x] = in[(size_t)(by + i) * C + x];
    __syncthreads();
    const int ox = by + threadIdx.x;
#pragma unroll
    for (int i = threadIdx.y; i < 32; i += 8)
        out[(size_t)(bx + i) * R + ox] = __float2half(tile[threadIdx.x][i]);
}

// =====================================================================
// Multi-section RoPE (in-place on g_qkv; writes present_k)
// =====================================================================
__device__ __forceinline__ int sec3(int d) {
    if (d < 16)  return 0;
    if (d < 40)  return 1;
    if (d < 64)  return 2;
    if (d < 80)  return 0;
    if (d < 104) return 1;
    return 2;
}

__global__ __launch_bounds__(64)
void rope_kernel(const float* __restrict__ cosb, const float* __restrict__ sinb,
                 float* __restrict__ out_k)
{
    const int unit = blockIdx.x;
    const int t  = unit / (N_HEADS + N_KVH);
    const int hh = unit % (N_HEADS + N_KVH);
    const int d  = threadIdx.x;
    const int d2 = d + 64;

    const float c1 = cosb[(size_t)sec3(d)  * T_SEQ * HEAD_D + (size_t)t * HEAD_D + d];
    const float s1 = sinb[(size_t)sec3(d)  * T_SEQ * HEAD_D + (size_t)t * HEAD_D + d];
    const float c2 = cosb[(size_t)sec3(d2) * T_SEQ * HEAD_D + (size_t)t * HEAD_D + d2];
    const float s2 = sinb[(size_t)sec3(d2) * T_SEQ * HEAD_D + (size_t)t * HEAD_D + d2];

    float* base = g_qkv + (size_t)t * QKV_W +
                  ((hh < N_HEADS) ? hh * HEAD_D : C_EMB + (hh - N_HEADS) * HEAD_D);

    float x1 = base[d];
    float x2 = base[d2];
    float r1 = x1 * c1 - x2 * s1;
    float r2 = x2 * c2 + x1 * s2;
    base[d]  = r1;
    base[d2] = r2;

    if (hh >= N_HEADS) {
        int h = hh - N_HEADS;
        out_k[(size_t)h * T_SEQ * HEAD_D + (size_t)t * HEAD_D + d]  = r1;
        out_k[(size_t)h * T_SEQ * HEAD_D + (size_t)t * HEAD_D + d2] = r2;
    }
}

__global__ __launch_bounds__(256)
void vcopy_kernel(float* __restrict__ out_v)
{
    int idx = blockIdx.x * 256 + threadIdx.x;
    if (idx >= N_KVH * T_SEQ * HEAD_D) return;
    int d = idx & (HEAD_D - 1);
    int t = (idx / HEAD_D) & (T_SEQ - 1);
    int h = idx / (HEAD_D * T_SEQ);
    out_v[idx] = g_qkv[(size_t)t * QKV_W + C_EMB + KV_W + h * HEAD_D + d];
}

// =====================================================================
// fp16 mma flash attention.
// Block: 256 threads (8 warps), 128 q rows, 1 head. K tiles of 32 keys.
// Q/K in smem half, 272B padded rows (conflict-free ldmatrix).
// V transposed in smem (Vt[d][key], 80B rows) -> PV B-frags identical
// to gemm_h's validated non-trans path. S accumulators convert directly
// into P A-fragments (FA2 layout identity).
// =====================================================================
#define ATQROWB 272
#define ATVROWB 80
#define ATSMEM  (128 * ATQROWB + 32 * ATQROWB + 128 * ATVROWB)  // 53760

__global__ __launch_bounds__(256, 2)
void attn_mma(__half* __restrict__ Y)
{
    extern __shared__ char sm[];
    char* Qs = sm;
    char* Ks = sm + 128 * ATQROWB;
    char* Vt = Ks + 32 * ATQROWB;
    const uint32_t qs = smem_u32(Qs);
    const uint32_t ks = smem_u32(Ks);
    const uint32_t vt = smem_u32(Vt);

    const int h    = blockIdx.y;
    const int kvh  = h >> 2;
    const int q0   = blockIdx.x * 128;
    const int tid  = threadIdx.x;
    const int warp = tid >> 5;
    const int lane = tid & 31;
    const int g    = lane >> 2;
    const int tg   = lane & 3;
    const int lr8  = lane & 7;
    const int rsel = (lane >> 3) & 1;
    const int ksel = (lane >> 4) & 1;
    const float scale = 0.08838834764831845f;

    // load Q tile [128][128] -> half smem
    for (int i = tid; i < 128 * 32; i += 256) {
        int row = i >> 5, c4 = (i & 31) * 4;
        float4 v = *(const float4*)&g_qkv[(size_t)(q0 + row) * QKV_W + h * HEAD_D + c4];
        char* p = Qs + row * ATQROWB + c4 * 2;
        *(__half2*)p       = __floats2half2_rn(v.x, v.y);
        *(__half2*)(p + 4) = __floats2half2_rn(v.z, v.w);
    }

    const uint32_t qa = qs + (uint32_t)((warp * 16 + lr8 + rsel * 8) * ATQROWB + ksel * 16);
    const uint32_t ka = ks + (uint32_t)((lr8 + ksel * 8) * ATQROWB + rsel * 16);
    const uint32_t va = vt + (uint32_t)((lr8 + ksel * 8) * ATVROWB + rsel * 16);

    float O[16][4];
#pragma unroll
    for (int n = 0; n < 16; n++)
#pragma unroll
        for (int r = 0; r < 4; r++) O[n][r] = 0.f;
    float m0 = -1e30f, m1 = -1e30f, l0 = 0.f, l1 = 0.f;

    const int row0 = q0 + warp * 16 + g;
    const int wlast = q0 + warp * 16 + 15;
    const int kend = q0 + 128;

    for (int kk0 = 0; kk0 < kend; kk0 += 32) {
        __syncthreads();
        // load K tile [32][128] -> half smem
        for (int i = tid; i < 32 * 32; i += 256) {
            int row = i >> 5, c4 = (i & 31) * 4;
            float4 v = *(const float4*)&g_qkv[(size_t)(kk0 + row) * QKV_W + C_EMB + kvh * HEAD_D + c4];
            char* p = Ks + row * ATQROWB + c4 * 2;
            *(__half2*)p       = __floats2half2_rn(v.x, v.y);
            *(__half2*)(p + 4) = __floats2half2_rn(v.z, v.w);
        }
        // load V tile transposed: Vt[d][key]
        for (int i = tid; i < 32 * 32; i += 256) {
            int key = i & 31, c4 = (i >> 5) * 4;
            float4 v = *(const float4*)&g_qkv[(size_t)(kk0 + key) * QKV_W + C_EMB + KV_W + kvh * HEAD_D + c4];
            char* p = Vt + key * 2;
            *(__half*)(p + (c4 + 0) * ATVROWB) = __float2half(v.x);
            *(__half*)(p + (c4 + 1) * ATVROWB) = __float2half(v.y);
            *(__half*)(p + (c4 + 2) * ATVROWB) = __float2half(v.z);
            *(__half*)(p + (c4 + 3) * ATVROWB) = __float2half(v.w);
        }
        __syncthreads();

        if (kk0 > wlast) continue;   // fully-masked tile for this warp

        // ---- S = Q @ K^T  (16 x 32 per warp) ----
        float S[4][4];
#pragma unroll
        for (int nt = 0; nt < 4; nt++)
#pragma unroll
            for (int r = 0; r < 4; r++) S[nt][r] = 0.f;

#pragma unroll
        for (int kc = 0; kc < 8; kc++) {
            unsigned aq[4], bk2[2][4];
            ldm_x4(aq, qa + (uint32_t)(kc * 32));
            ldm_x4(bk2[0], ka + (uint32_t)(kc * 32));
            ldm_x4(bk2[1], ka + (uint32_t)(16 * ATQROWB + kc * 32));
#pragma unroll
            for (int nt = 0; nt < 4; nt++)
                mma_f16(S[nt], aq, &bk2[nt >> 1][(nt & 1) * 2]);
        }

        // ---- mask + scale + online softmax ----
        float rm0 = -1e30f, rm1 = -1e30f;
#pragma unroll
        for (int nt = 0; nt < 4; nt++) {
            int cb = kk0 + nt * 8 + 2 * tg;
            S[nt][0] = (cb     <= row0)     ? S[nt][0] * scale : -1e30f;
            S[nt][1] = (cb + 1 <= row0)     ? S[nt][1] * scale : -1e30f;
            S[nt][2] = (cb     <= row0 + 8) ? S[nt][2] * scale : -1e30f;
            S[nt][3] = (cb + 1 <= row0 + 8) ? S[nt][3] * scale : -1e30f;
            rm0 = fmaxf(rm0, fmaxf(S[nt][0], S[nt][1]));
            rm1 = fmaxf(rm1, fmaxf(S[nt][2], S[nt][3]));
        }
        rm0 = fmaxf(rm0, __shfl_xor_sync(0xffffffffu, rm0, 1));
        rm0 = fmaxf(rm0, __shfl_xor_sync(0xffffffffu, rm0, 2));
        rm1 = fmaxf(rm1, __shfl_xor_sync(0xffffffffu, rm1, 1));
        rm1 = fmaxf(rm1, __shfl_xor_sync(0xffffffffu, rm1, 2));

        float mn0 = fmaxf(m0, rm0), mn1 = fmaxf(m1, rm1);
        float c0 = __expf(m0 - mn0), c1 = __expf(m1 - mn1);
        float s0 = 0.f, s1 = 0.f;
#pragma unroll
        for (int nt = 0; nt < 4; nt++) {
            S[nt][0] = __expf(S[nt][0] - mn0);
            S[nt][1] = __expf(S[nt][1] - mn0);
            S[nt][2] = __expf(S[nt][2] - mn1);
            S[nt][3] = __expf(S[nt][3] - mn1);
            s0 += S[nt][0] + S[nt][1];
            s1 += S[nt][2] + S[nt][3];
        }
        s0 += __shfl_xor_sync(0xffffffffu, s0, 1);
        s0 += __shfl_xor_sync(0xffffffffu, s0, 2);
        s1 += __shfl_xor_sync(0xffffffffu, s1, 1);
        s1 += __shfl_xor_sync(0xffffffffu, s1, 2);
        l0 = l0 * c0 + s0;
        l1 = l1 * c1 + s1;
        m0 = mn0; m1 = mn1;
#pragma unroll
        for (int n = 0; n < 16; n++) {
            O[n][0] *= c0; O[n][1] *= c0;
            O[n][2] *= c1; O[n][3] *= c1;
        }

        // ---- O += P @ V ----
#pragma unroll
        for (int kc = 0; kc < 2; kc++) {
            unsigned pa[4];
            pa[0] = pack_h2(S[2 * kc][0],     S[2 * kc][1]);
            pa[1] = pack_h2(S[2 * kc][2],     S[2 * kc][3]);
            pa[2] = pack_h2(S[2 * kc + 1][0], S[2 * kc + 1][1]);
            pa[3] = pack_h2(S[2 * kc + 1][2], S[2 * kc + 1][3]);
#pragma unroll
            for (int pr = 0; pr < 8; pr++) {
                unsigned vb[4];
                ldm_x4(vb, va + (uint32_t)(pr * 16 * ATVROWB + kc * 32));
                mma_f16(O[pr * 2],     pa, &vb[0]);
                mma_f16(O[pr * 2 + 1], pa, &vb[2]);
            }
        }
    }

    // epilogue: normalize, write half
    float inv0 = 1.f / l0, inv1 = 1.f / l1;
#pragma unroll
    for (int n = 0; n < 16; n++) {
        int c = h * HEAD_D + n * 8 + 2 * tg;
        __half2 h0 = __floats2half2_rn(O[n][0] * inv0, O[n][1] * inv0);
        __half2 h1 = __floats2half2_rn(O[n][2] * inv1, O[n][3] * inv1);
        *(__half2*)&Y[(size_t)row0 * C_EMB + c]       = h0;
        *(__half2*)&Y[(size_t)(row0 + 8) * C_EMB + c] = h1;
    }
}

// =====================================================================
// launch
// =====================================================================
extern "C" void kernel_launch(void* const* d_in, const int* in_sizes, int n_in,
                              void* d_out, int out_size)
{
    (void)in_sizes; (void)n_in; (void)out_size;
    const float* x    = (const float*)d_in[0];
    const float* cosb = (const float*)d_in[1];
    const float* sinb = (const float*)d_in[2];
    const float* Wq   = (const float*)d_in[3];
    const float* bq   = (const float*)d_in[4];
    const float* Wk   = (const float*)d_in[5];
    const float* bk   = (const float*)d_in[6];
    const float* Wv   = (const float*)d_in[7];
    const float* bv   = (const float*)d_in[8];
    const float* Wo   = (const float*)d_in[9];

    float* out   = (float*)d_out;
    float* out_y = out;
    float* out_k = out + (size_t)T_SEQ * C_EMB;
    float* out_v = out_k + (size_t)N_KVH * T_SEQ * HEAD_D;

    float*  qkvb; cudaGetSymbolAddress((void**)&qkvb, g_qkv);
    __half* yhb;  cudaGetSymbolAddress((void**)&yhb,  g_yh);
    __half* xhb;  cudaGetSymbolAddress((void**)&xhb,  g_xh);
    __half* wqkv; cudaGetSymbolAddress((void**)&wqkv, g_wqkvt);
    __half* wot;  cudaGetSymbolAddress((void**)&wot,  g_wot);
    float*  bqkv; cudaGetSymbolAddress((void**)&bqkv, g_bqkv);

    cudaFuncSetAttribute(gemm_h, cudaFuncAttributeMaxDynamicSharedMemorySize, GSMEM);
    cudaFuncSetAttribute(attn_mma, cudaFuncAttributeMaxDynamicSharedMemorySize, ATSMEM);

    // 1: fused weight transposes + bias concat
    transpose_all<<<dim3(64, 64, 5), dim3(32, 8)>>>(Wq, Wk, Wv, Wo, bq, bk, bv);

    // 2: x -> half
    convx_kernel<<<(T_SEQ * C_EMB / 4) / 256, 256>>>(x);

    // 3: fused QKV projection (384 CTAs — full fill)
    gemm_h<<<dim3(QKV_W / 128, T_SEQ / 128), 256, GSMEM>>>(xhb, wqkv, bqkv, qkvb, T_SEQ, QKV_W, C_EMB);

    // 4: RoPE (also writes present_k)
    rope_kernel<<<T_SEQ * (N_HEADS + N_KVH), 64>>>(cosb, sinb, out_k);

    // 5: present_v
    vcopy_kernel<<<(N_KVH * T_SEQ * HEAD_D + 255) / 256, 256>>>(out_v);

    // 6: mma flash attention  (the ncu-captured launch)
    attn_mma<<<dim3(T_SEQ / 128, N_HEADS), 256, ATSMEM>>>(yhb);

    // 7: output projection
    gemm_h<<<dim3(C_EMB / 128, T_SEQ / 128), 256, GSMEM>>>(yhb, wot, nullptr, out_y, T_SEQ, C_EMB, C_EMB);
}

// round 9
// speedup vs baseline: 7.8185x; 1.2624x over previous
#include <cuda_runtime.h>
#include <cuda_fp16.h>
#include <math.h>
#include <cstdint>

// Problem constants
#define T_SEQ   2048
#define C_EMB   2048
#define N_HEADS 16
#define N_KVH   4
#define HEAD_D  128
#define KV_W    (N_KVH * HEAD_D)   // 512
#define QKV_W   (C_EMB + 2 * KV_W) // 3072

// -------- scratch (device globals; no allocation allowed) --------
__device__ float  g_qkv[T_SEQ * QKV_W];     // fused QKV output [T, 3072] fp32
__device__ __half g_qh[T_SEQ * C_EMB];      // roped Q half [t][h*128+d]
__device__ __half g_kh[N_KVH * T_SEQ * HEAD_D]; // roped K half [kvh][t][d]
__device__ __half g_vh[N_KVH * T_SEQ * HEAD_D]; // V half [kvh][t][d]
__device__ __half g_yh[T_SEQ * C_EMB];      // attention out (half)
__device__ __half g_xh[T_SEQ * C_EMB];      // x in half
__device__ __half g_wqkvt[QKV_W * C_EMB];   // concat transposed weights [3072, 2048]
__device__ __half g_wot[C_EMB * C_EMB];
__device__ float  g_bqkv[QKV_W];            // concat bias

// =====================================================================
// helpers
// =====================================================================
__device__ __forceinline__ uint32_t smem_u32(const void* p) {
    uint32_t a;
    asm("{ .reg .u64 t; cvta.to.shared.u64 t, %1; cvt.u32.u64 %0, t; }" : "=r"(a) : "l"(p));
    return a;
}
__device__ __forceinline__ void cp_async16(uint32_t dst, const void* src) {
    asm volatile("cp.async.ca.shared.global [%0], [%1], 16;" :: "r"(dst), "l"(src) : "memory");
}
__device__ __forceinline__ void cp_commit() {
    asm volatile("cp.async.commit_group;" ::: "memory");
}
template <int N>
__device__ __forceinline__ void cp_wait() {
    asm volatile("cp.async.wait_group %0;" :: "n"(N) : "memory");
}
__device__ __forceinline__ void ldm_x4(unsigned* r, uint32_t addr) {
    asm volatile("ldmatrix.sync.aligned.m8n8.x4.shared.b16 {%0,%1,%2,%3}, [%4];"
        : "=r"(r[0]), "=r"(r[1]), "=r"(r[2]), "=r"(r[3]) : "r"(addr));
}
__device__ __forceinline__ void ldm_x4t(unsigned* r, uint32_t addr) {
    asm volatile("ldmatrix.sync.aligned.m8n8.x4.trans.shared.b16 {%0,%1,%2,%3}, [%4];"
        : "=r"(r[0]), "=r"(r[1]), "=r"(r[2]), "=r"(r[3]) : "r"(addr));
}
__device__ __forceinline__ void mma_f16(float* c, const unsigned* a, const unsigned* b) {
    asm volatile(
        "mma.sync.aligned.m16n8k16.row.col.f32.f16.f16.f32 "
        "{%0,%1,%2,%3}, {%4,%5,%6,%7}, {%8,%9}, {%0,%1,%2,%3};"
        : "+f"(c[0]), "+f"(c[1]), "+f"(c[2]), "+f"(c[3])
        : "r"(a[0]), "r"(a[1]), "r"(a[2]), "r"(a[3]), "r"(b[0]), "r"(b[1]));
}
__device__ __forceinline__ unsigned pack_h2(float a, float b) {
    __half2 h = __floats2half2_rn(a, b);
    return *reinterpret_cast<unsigned*>(&h);
}

// =====================================================================
// fp16 mma GEMM (validated R6-R8)
// =====================================================================
#define GSTAGES   4
#define GROWB     80
#define STAGE_A   (128 * GROWB)
#define STAGE_SZ  (2 * STAGE_A)
#define GSMEM     (GSTAGES * STAGE_SZ)

__global__ __launch_bounds__(256, 2)
void gemm_h(const __half* __restrict__ A, const __half* __restrict__ Bt,
            const float* __restrict__ bias, float* __restrict__ C,
            int M, int N, int K)
{
    extern __shared__ char smem[];
    const uint32_t sbase = smem_u32(smem);

    const int tid  = threadIdx.x;
    const int warp = tid >> 5;
    const int lane = tid & 31;
    const int g    = lane >> 2;
    const int tg   = lane & 3;
    const int wm   = warp >> 2;
    const int wn   = warp & 3;
    const int m0   = blockIdx.y * 128;
    const int n0   = blockIdx.x * 128;

    const int lrow = tid & 127;
    const int isB  = tid >> 7;
    const __half* src = isB ? (Bt + (size_t)(n0 + lrow) * K)
                            : (A  + (size_t)(m0 + lrow) * K);
    const uint32_t dst0 = (uint32_t)(isB * STAGE_A + lrow * GROWB);
    const int KT = K / 32;

    const int lr8  = lane & 7;
    const int rsel = (lane >> 3) & 1;
    const int ksel = (lane >> 4) & 1;
    const uint32_t a_base = sbase +
        (uint32_t)((wm * 64 + lr8 + rsel * 8) * GROWB + ksel * 16);
    const uint32_t b_base = sbase + STAGE_A +
        (uint32_t)((wn * 32 + lr8 + ksel * 8) * GROWB + rsel * 16);

    float acc[4][4][4];
#pragma unroll
    for (int mt = 0; mt < 4; mt++)
#pragma unroll
        for (int nt = 0; nt < 4; nt++)
#pragma unroll
            for (int r = 0; r < 4; r++) acc[mt][nt][r] = 0.f;

#pragma unroll
    for (int s = 0; s < GSTAGES - 1; s++) {
        uint32_t d = sbase + s * STAGE_SZ + dst0;
        const __half* sp = src + (size_t)s * 32;
#pragma unroll
        for (int c = 0; c < 4; c++) cp_async16(d + c * 16, sp + c * 8);
        cp_commit();
    }

    for (int kt = 0; kt < KT; kt++) {
        cp_wait<GSTAGES - 2>();
        __syncthreads();

        if (kt + GSTAGES - 1 < KT) {
            int s = (kt + GSTAGES - 1) & (GSTAGES - 1);
            uint32_t d = sbase + s * STAGE_SZ + dst0;
            const __half* sp = src + (size_t)(kt + GSTAGES - 1) * 32;
#pragma unroll
            for (int c = 0; c < 4; c++) cp_async16(d + c * 16, sp + c * 8);
        }
        cp_commit();

        const int slot = kt & (GSTAGES - 1);
        const uint32_t soff = (uint32_t)(slot * STAGE_SZ);

#pragma unroll
        for (int ks = 0; ks < 2; ks++) {
            unsigned af[4][4], bf[2][4];
#pragma unroll
            for (int mt = 0; mt < 4; mt++)
                ldm_x4(af[mt], a_base + soff + (uint32_t)(mt * 16 * GROWB + ks * 32));
#pragma unroll
            for (int pr = 0; pr < 2; pr++)
                ldm_x4(bf[pr], b_base + soff + (uint32_t)(pr * 16 * GROWB + ks * 32));
#pragma unroll
            for (int mt = 0; mt < 4; mt++)
#pragma unroll
                for (int nt = 0; nt < 4; nt++)
                    mma_f16(acc[mt][nt], af[mt], &bf[nt >> 1][(nt & 1) * 2]);
        }
    }

#pragma unroll
    for (int mt = 0; mt < 4; mt++) {
        int r0 = m0 + wm * 64 + mt * 16 + g;
#pragma unroll
        for (int nt = 0; nt < 4; nt++) {
            int c = n0 + wn * 32 + nt * 8 + 2 * tg;
            float bx = 0.f, by = 0.f;
            if (bias) { bx = bias[c]; by = bias[c + 1]; }
            float2 v0 = make_float2(acc[mt][nt][0] + bx, acc[mt][nt][1] + by);
            float2 v1 = make_float2(acc[mt][nt][2] + bx, acc[mt][nt][3] + by);
            *(float2*)&C[(size_t)r0 * N + c]       = v0;
            *(float2*)&C[(size_t)(r0 + 8) * N + c] = v1;
        }
    }
}

// =====================================================================
// x -> half
// =====================================================================
__global__ __launch_bounds__(256)
void convx_kernel(const float* __restrict__ x)
{
    int i = (blockIdx.x * 256 + threadIdx.x) * 4;
    float4 v = *(const float4*)&x[i];
    *(__half2*)&g_xh[i]     = __floats2half2_rn(v.x, v.y);
    *(__half2*)&g_xh[i + 2] = __floats2half2_rn(v.z, v.w);
}

// =====================================================================
// fused transpose of weights into g_wqkvt / g_wot, + bias concat (z==4)
// =====================================================================
__global__ __launch_bounds__(256)
void transpose_all(const float* __restrict__ Wq, const float* __restrict__ Wk,
                   const float* __restrict__ Wv, const float* __restrict__ Wo,
                   const float* __restrict__ bq, const float* __restrict__ bk,
                   const float* __restrict__ bv)
{
    const int z = blockIdx.z;
    if (z == 4) {
        if (blockIdx.y == 0 && blockIdx.x < 12) {
            int idx = blockIdx.x * 256 + threadIdx.y * 32 + threadIdx.x;
            float v = (idx < 2048) ? bq[idx]
                    : (idx < 2560) ? bk[idx - 2048]
                                   : bv[idx - 2560];
            g_bqkv[idx] = v;
        }
        return;
    }
    __shared__ float tile[32][33];
    const float* in;
    __half* out;
    int C;
    if (z == 0)      { in = Wq; out = g_wqkvt;               C = C_EMB; }
    else if (z == 1) { in = Wk; out = g_wqkvt + 2048 * 2048; C = KV_W; }
    else if (z == 2) { in = Wv; out = g_wqkvt + 2560 * 2048; C = KV_W; }
    else             { in = Wo; out = g_wot;                 C = C_EMB; }
    const int bx = blockIdx.x * 32;
    if (bx >= C) return;
    const int by = blockIdx.y * 32;
    const int R = C_EMB;
    const int x = bx + threadIdx.x;
#pragma unroll
    for (int i = threadIdx.y; i < 32; i += 8)
        tile[i][threadIdx.x] = in[(size_t)(by + i) * C + x];
    __syncthreads();
    const int ox = by + threadIdx.x;
#pragma unroll
    for (int i = threadIdx.y; i < 32; i += 8)
        out[(size_t)(bx + i) * R + ox] = __float2half(tile[threadIdx.x][i]);
}

// =====================================================================
// RoPE + V copy, one t per block (256 threads). cos/sin cached in smem.
// Writes: g_qh (half roped Q), g_kh + out_k (roped K), g_vh + out_v (V).
// =====================================================================
__device__ __forceinline__ int sec3(int d) {
    if (d < 16)  return 0;
    if (d < 40)  return 1;
    if (d < 64)  return 2;
    if (d < 80)  return 0;
    if (d < 104) return 1;
    return 2;
}

__global__ __launch_bounds__(256)
void rope2_kernel(const float* __restrict__ cosb, const float* __restrict__ sinb,
                  float* __restrict__ out_k, float* __restrict__ out_v)
{
    __shared__ float cs[384], sn[384];
    const int t   = blockIdx.x;
    const int tid = threadIdx.x;

    // cache cos/sin rows for this t: [3][128]
    for (int i = tid; i < 384; i += 256) {
        int ch = i >> 7, d = i & 127;
        cs[i] = cosb[(size_t)ch * T_SEQ * HEAD_D + (size_t)t * HEAD_D + d];
        sn[i] = sinb[(size_t)ch * T_SEQ * HEAD_D + (size_t)t * HEAD_D + d];
    }
    __syncthreads();

    const float* row = g_qkv + (size_t)t * QKV_W;

    // 20 heads x 64 pairs = 1280 pairs
#pragma unroll
    for (int it = 0; it < 5; it++) {
        int p  = it * 256 + tid;
        int hh = p >> 6;
        int d  = p & 63;
        int d2 = d + 64;
        float c1 = cs[sec3(d)  * 128 + d],  s1 = sn[sec3(d)  * 128 + d];
        float c2 = cs[sec3(d2) * 128 + d2], s2 = sn[sec3(d2) * 128 + d2];

        const float* base = row + ((hh < N_HEADS) ? hh * HEAD_D
                                                  : C_EMB + (hh - N_HEADS) * HEAD_D);
        float x1 = base[d], x2 = base[d2];
        float r1 = x1 * c1 - x2 * s1;
        float r2 = x2 * c2 + x1 * s2;

        if (hh < N_HEADS) {
            g_qh[(size_t)t * C_EMB + hh * HEAD_D + d]  = __float2half(r1);
            g_qh[(size_t)t * C_EMB + hh * HEAD_D + d2] = __float2half(r2);
        } else {
            int h = hh - N_HEADS;
            size_t o = (size_t)h * T_SEQ * HEAD_D + (size_t)t * HEAD_D;
            out_k[o + d]  = r1;
            out_k[o + d2] = r2;
            g_kh[o + d]   = __float2half(r1);
            g_kh[o + d2]  = __float2half(r2);
        }
    }

    // V: 4 heads x 128 = 512 elements
#pragma unroll
    for (int it = 0; it < 2; it++) {
        int idx = it * 256 + tid;
        int h = idx >> 7, d = idx & 127;
        float v = row[C_EMB + KV_W + idx];
        size_t o = (size_t)h * T_SEQ * HEAD_D + (size_t)t * HEAD_D + d;
        out_v[o] = v;
        g_vh[o]  = __float2half(v);
    }
}

// =====================================================================
// fp16 mma flash attention v2.
// 256 threads / 8 warps, 128 q rows, 1 head. 32-key K/V tiles,
// cp.async double-buffered from half buffers. V row-major in smem;
// PV B-fragments via ldmatrix.x4.trans.
// =====================================================================
#define AROWB   272                          // 128 halves + 16B pad
#define AQ_SZ   (128 * AROWB)                // 34816
#define AKV_SZ  (32 * AROWB)                 // 8704
#define ATSMEM  (AQ_SZ + 4 * AKV_SZ)         // 69632

__global__ __launch_bounds__(256, 2)
void attn_mma(__half* __restrict__ Y)
{
    extern __shared__ char sm[];
    const uint32_t qs  = smem_u32(sm);
    const uint32_t ks0 = qs + AQ_SZ;          // K buffers: ks0, ks0+AKV_SZ
    const uint32_t vs0 = ks0 + 2 * AKV_SZ;    // V buffers

    const int h    = blockIdx.y;
    const int kvh  = h >> 2;
    const int q0   = blockIdx.x * 128;
    const int tid  = threadIdx.x;
    const int warp = tid >> 5;
    const int lane = tid & 31;
    const int g    = lane >> 2;
    const int tg   = lane & 3;
    const int lr8  = lane & 7;
    const int rsel = (lane >> 3) & 1;
    const int ksel = (lane >> 4) & 1;
    const float scale = 0.08838834764831845f;

    const __half* Ksrc = g_kh + (size_t)kvh * T_SEQ * HEAD_D;
    const __half* Vsrc = g_vh + (size_t)kvh * T_SEQ * HEAD_D;

    // Q tile: 128 rows x 256B, cp.async
    {
        const __half* Qsrc = g_qh + (size_t)q0 * C_EMB + h * HEAD_D;
        for (int i = tid; i < 128 * 16; i += 256) {
            int row = i >> 4, c = i & 15;
            cp_async16(qs + (uint32_t)(row * AROWB + c * 16),
                       Qsrc + (size_t)row * C_EMB + c * 8);
        }
        cp_commit();
    }

    const int ntiles = q0 / 32 + 4;

    // preload tile 0 into buffer 0 (K + V)
    for (int i = tid; i < 32 * 16; i += 256) {
        int row = i >> 4, c = i & 15;
        cp_async16(ks0 + (uint32_t)(row * AROWB + c * 16),
                   Ksrc + (size_t)row * HEAD_D + c * 8);
        cp_async16(vs0 + (uint32_t)(row * AROWB + c * 16),
                   Vsrc + (size_t)row * HEAD_D + c * 8);
    }
    cp_commit();

    const uint32_t qa = qs + (uint32_t)((warp * 16 + lr8 + rsel * 8) * AROWB + ksel * 16);

    float O[16][4];
#pragma unroll
    for (int n = 0; n < 16; n++)
#pragma unroll
        for (int r = 0; r < 4; r++) O[n][r] = 0.f;
    float m0 = -1e30f, m1 = -1e30f, l0 = 0.f, l1 = 0.f;

    const int row0  = q0 + warp * 16 + g;
    const int wlast = q0 + warp * 16 + 15;

    for (int kt = 0; kt < ntiles; kt++) {
        // issue tile kt+1 into buffer (kt+1)&1
        if (kt + 1 < ntiles) {
            const uint32_t kb = ks0 + (uint32_t)(((kt + 1) & 1) * AKV_SZ);
            const uint32_t vb = vs0 + (uint32_t)(((kt + 1) & 1) * AKV_SZ);
            const __half* Ki = Ksrc + (size_t)(kt + 1) * 32 * HEAD_D;
            const __half* Vi = Vsrc + (size_t)(kt + 1) * 32 * HEAD_D;
            for (int i = tid; i < 32 * 16; i += 256) {
                int row = i >> 4, c = i & 15;
                cp_async16(kb + (uint32_t)(row * AROWB + c * 16),
                           Ki + (size_t)row * HEAD_D + c * 8);
                cp_async16(vb + (uint32_t)(row * AROWB + c * 16),
                           Vi + (size_t)row * HEAD_D + c * 8);
            }
            cp_commit();
            cp_wait<1>();
        } else {
            cp_wait<0>();
        }
        __syncthreads();

        const int kk0 = kt * 32;
        const uint32_t kbuf = ks0 + (uint32_t)((kt & 1) * AKV_SZ);
        const uint32_t vbuf = vs0 + (uint32_t)((kt & 1) * AKV_SZ);

        if (kk0 <= wlast) {
            const uint32_t ka = kbuf + (uint32_t)((lr8 + ksel * 8) * AROWB + rsel * 16);

            // ---- S = Q @ K^T ----
            float S[4][4];
#pragma unroll
            for (int nt = 0; nt < 4; nt++)
#pragma unroll
                for (int r = 0; r < 4; r++) S[nt][r] = 0.f;

#pragma unroll
            for (int kc = 0; kc < 8; kc++) {
                unsigned aq[4], bk2[2][4];
                ldm_x4(aq, qa + (uint32_t)(kc * 32));
                ldm_x4(bk2[0], ka + (uint32_t)(kc * 32));
                ldm_x4(bk2[1], ka + (uint32_t)(16 * AROWB + kc * 32));
#pragma unroll
                for (int nt = 0; nt < 4; nt++)
                    mma_f16(S[nt], aq, &bk2[nt >> 1][(nt & 1) * 2]);
            }

            // ---- mask + online softmax ----
            float rm0 = -1e30f, rm1 = -1e30f;
#pragma unroll
            for (int nt = 0; nt < 4; nt++) {
                int cb = kk0 + nt * 8 + 2 * tg;
                S[nt][0] = (cb     <= row0)     ? S[nt][0] * scale : -1e30f;
                S[nt][1] = (cb + 1 <= row0)     ? S[nt][1] * scale : -1e30f;
                S[nt][2] = (cb     <= row0 + 8) ? S[nt][2] * scale : -1e30f;
                S[nt][3] = (cb + 1 <= row0 + 8) ? S[nt][3] * scale : -1e30f;
                rm0 = fmaxf(rm0, fmaxf(S[nt][0], S[nt][1]));
                rm1 = fmaxf(rm1, fmaxf(S[nt][2], S[nt][3]));
            }
            rm0 = fmaxf(rm0, __shfl_xor_sync(0xffffffffu, rm0, 1));
            rm0 = fmaxf(rm0, __shfl_xor_sync(0xffffffffu, rm0, 2));
            rm1 = fmaxf(rm1, __shfl_xor_sync(0xffffffffu, rm1, 1));
            rm1 = fmaxf(rm1, __shfl_xor_sync(0xffffffffu, rm1, 2));

            float mn0 = fmaxf(m0, rm0), mn1 = fmaxf(m1, rm1);
            float c0 = __expf(m0 - mn0), c1 = __expf(m1 - mn1);
            float s0 = 0.f, s1 = 0.f;
#pragma unroll
            for (int nt = 0; nt < 4; nt++) {
                S[nt][0] = __expf(S[nt][0] - mn0);
                S[nt][1] = __expf(S[nt][1] - mn0);
                S[nt][2] = __expf(S[nt][2] - mn1);
                S[nt][3] = __expf(S[nt][3] - mn1);
                s0 += S[nt][0] + S[nt][1];
                s1 += S[nt][2] + S[nt][3];
            }
            s0 += __shfl_xor_sync(0xffffffffu, s0, 1);
            s0 += __shfl_xor_sync(0xffffffffu, s0, 2);
            s1 += __shfl_xor_sync(0xffffffffu, s1, 1);
            s1 += __shfl_xor_sync(0xffffffffu, s1, 2);
            l0 = l0 * c0 + s0;
            l1 = l1 * c1 + s1;
            m0 = mn0; m1 = mn1;
#pragma unroll
            for (int n = 0; n < 16; n++) {
                O[n][0] *= c0; O[n][1] *= c0;
                O[n][2] *= c1; O[n][3] *= c1;
            }

            // ---- O += P @ V  (V row-major, B-frags via ldmatrix.trans) ----
#pragma unroll
            for (int kc = 0; kc < 2; kc++) {
                unsigned pa[4];
                pa[0] = pack_h2(S[2 * kc][0],     S[2 * kc][1]);
                pa[1] = pack_h2(S[2 * kc][2],     S[2 * kc][3]);
                pa[2] = pack_h2(S[2 * kc + 1][0], S[2 * kc + 1][1]);
                pa[3] = pack_h2(S[2 * kc + 1][2], S[2 * kc + 1][3]);
                // trans address: row = key (kc*16 + lr8 + rsel*8), col byte = ksel*16
                const uint32_t va = vbuf +
                    (uint32_t)((kc * 16 + lr8 + rsel * 8) * AROWB + ksel * 16);
#pragma unroll
                for (int dc = 0; dc < 8; dc++) {
                    unsigned vb[4];
                    ldm_x4t(vb, va + (uint32_t)(dc * 32));
                    mma_f16(O[dc * 2],     pa, &vb[0]);
                    mma_f16(O[dc * 2 + 1], pa, &vb[2]);
                }
            }
        }
        __syncthreads();
    }

    // epilogue
    float inv0 = 1.f / l0, inv1 = 1.f / l1;
#pragma unroll
    for (int n = 0; n < 16; n++) {
        int c = h * HEAD_D + n * 8 + 2 * tg;
        __half2 h0 = __floats2half2_rn(O[n][0] * inv0, O[n][1] * inv0);
        __half2 h1 = __floats2half2_rn(O[n][2] * inv1, O[n][3] * inv1);
        *(__half2*)&Y[(size_t)row0 * C_EMB + c]       = h0;
        *(__half2*)&Y[(size_t)(row0 + 8) * C_EMB + c] = h1;
    }
}

// =====================================================================
// launch
// =====================================================================
extern "C" void kernel_launch(void* const* d_in, const int* in_sizes, int n_in,
                              void* d_out, int out_size)
{
    (void)in_sizes; (void)n_in; (void)out_size;
    const float* x    = (const float*)d_in[0];
    const float* cosb = (const float*)d_in[1];
    const float* sinb = (const float*)d_in[2];
    const float* Wq   = (const float*)d_in[3];
    const float* bq   = (const float*)d_in[4];
    const float* Wk   = (const float*)d_in[5];
    const float* bk   = (const float*)d_in[6];
    const float* Wv   = (const float*)d_in[7];
    const float* bv   = (const float*)d_in[8];
    const float* Wo   = (const float*)d_in[9];

    float* out   = (float*)d_out;
    float* out_y = out;
    float* out_k = out + (size_t)T_SEQ * C_EMB;
    float* out_v = out_k + (size_t)N_KVH * T_SEQ * HEAD_D;

    float*  qkvb; cudaGetSymbolAddress((void**)&qkvb, g_qkv);
    __half* yhb;  cudaGetSymbolAddress((void**)&yhb,  g_yh);
    __half* xhb;  cudaGetSymbolAddress((void**)&xhb,  g_xh);
    __half* wqkv; cudaGetSymbolAddress((void**)&wqkv, g_wqkvt);
    __half* wot;  cudaGetSymbolAddress((void**)&wot,  g_wot);
    float*  bqkv; cudaGetSymbolAddress((void**)&bqkv, g_bqkv);

    cudaFuncSetAttribute(gemm_h, cudaFuncAttributeMaxDynamicSharedMemorySize, GSMEM);
    cudaFuncSetAttribute(attn_mma, cudaFuncAttributeMaxDynamicSharedMemorySize, ATSMEM);

    // 1: fused weight transposes + bias concat
    transpose_all<<<dim3(64, 64, 5), dim3(32, 8)>>>(Wq, Wk, Wv, Wo, bq, bk, bv);

    // 2: x -> half
    convx_kernel<<<(T_SEQ * C_EMB / 4) / 256, 256>>>(x);

    // 3: fused QKV projection (384 CTAs)
    gemm_h<<<dim3(QKV_W / 128, T_SEQ / 128), 256, GSMEM>>>(xhb, wqkv, bqkv, qkvb, T_SEQ, QKV_W, C_EMB);

    // 4: RoPE + V copy (writes present_k/present_v + half QKV buffers)
    rope2_kernel<<<T_SEQ, 256>>>(cosb, sinb, out_k, out_v);

    // 5: flash attention
    attn_mma<<<dim3(T_SEQ / 128, N_HEADS), 256, ATSMEM>>>(yhb);

    // 6: output projection (ncu-captured launch — full-fill GEMM profile)
    gemm_h<<<dim3(C_EMB / 128, T_SEQ / 128), 256, GSMEM>>>(yhb, wot, nullptr, out_y, T_SEQ, C_EMB, C_EMB);
}